// round 14
// baseline (speedup 1.0000x reference)
#include <cuda_runtime.h>
#include <cuda_bf16.h>
#include <math.h>
#include <stdint.h>

#define Bc 64
#define Sc 128
#define Tc 64
#define Hc 512
#define Vc 32000
#define NBLK 64
#define NLOGITS (16 * 250)   // 16 m-tiles (M=256) x 250 n-tiles
#define MEGA_SMEM (120 * 1024)

typedef __nv_bfloat16 bf16;

// ---------------- scratch (device globals: no allocs allowed) ----------------
__device__ __align__(16) float g_Uk[(size_t)Bc * Sc * Hc];       // 16 MB
__device__ __align__(16) float g_encW[(size_t)Bc * Sc * 1536];   // 50 MB: enc @ WihC^T
__device__ __align__(16) float g_h[Bc * Hc];
__device__ __align__(16) bf16  g_hhi[Bc * Hc], g_hlo[Bc * Hc];
__device__ __align__(16) float g_A4[4 * Bc * 2048];              // K-split partials [hwa|gh]
__device__ __align__(16) float g_giE[(size_t)Tc * Bc * 3 * Hc];  // 25 MB
__device__ __align__(16) bf16  g_xeH[(size_t)Tc * Bc * Hc], g_xeL[(size_t)Tc * Bc * Hc];
__device__ __align__(16) bf16  g_hallH[(size_t)Tc * Bc * Hc];
__device__ __align__(16) bf16  g_WoutH[(size_t)Vc * Hc], g_WoutL[(size_t)Vc * Hc];
__device__ __align__(16) bf16  g_BcatH[2048 * Hc], g_BcatL[2048 * Hc]; // [WaT|W_hh]
__device__ __align__(16) bf16  g_WihEH[3 * Hc * Hc], g_WihEL[3 * Hc * Hc];
__device__ __align__(16) bf16  g_WihCH[3 * Hc * Hc], g_WihCL[3 * Hc * Hc];
__device__ __align__(16) bf16  g_UaTH[Hc * Hc], g_UaTL[Hc * Hc];
__device__ __align__(16) bf16  g_encH[(size_t)Bc * Sc * Hc], g_encL[(size_t)Bc * Sc * Hc];
__device__ float g_rowsum[Bc * Tc];   // per-output-row sum of exp(logits)
__device__ unsigned int g_barrier;
__device__ unsigned int g_tstep;

__device__ __forceinline__ float sigm(float x) { return 1.0f / (1.0f + expf(-x)); }
__device__ __forceinline__ float fast_tanh(float x) {
    float y; asm("tanh.approx.f32 %0, %1;" : "=f"(y) : "f"(x)); return y;
}
__device__ __forceinline__ void split2(float x, bf16* hi, bf16* lo) {
    bf16 h = __float2bfloat16(x);
    *hi = h;
    *lo = __float2bfloat16(x - __bfloat162float(h));
}
// FMA-pipe exp (avoids MUFU EX2): 2^(x*log2e) via deg-5 poly.
__device__ __forceinline__ float fexp(float x) {
    float y = x * 1.44269504f;
    y = fminf(fmaxf(y, -60.f), 60.f);
    int i = __float2int_rn(y);
    float f = y - (float)i;
    float p = 1.3333558e-3f;
    p = fmaf(p, f, 9.618129e-3f);
    p = fmaf(p, f, 5.550411e-2f);
    p = fmaf(p, f, 2.402265e-1f);
    p = fmaf(p, f, 6.931472e-1f);
    p = fmaf(p, f, 1.0f);
    return p * __int_as_float((i + 127) << 23);
}

// ---------------- ONE fused prep kernel (all conversions + init + gather) ----
#define PR_WOUT   16000                 // Wout split
#define PR_WHH    (PR_WOUT + 768)       // W_hh -> Bcat tail
#define PR_WAT    (PR_WHH + 1024)       // Wa^T -> Bcat head
#define PR_UAT    (PR_WAT + 1024)       // Ua^T
#define PR_WIH    (PR_UAT + 3072)       // Wih E/C split
#define PR_ENC    (PR_WIH + 4096)       // enc split
#define PR_INIT   (PR_ENC + 128)        // h init + flags
#define PR_XE     (PR_INIT + 4096)      // emb gather

__global__ __launch_bounds__(256) void prep_kernel(
    const float* __restrict__ Wout, const float* __restrict__ W_hh,
    const float* __restrict__ Wa, const float* __restrict__ Ua,
    const float* __restrict__ W_ih, const float* __restrict__ enc,
    const float* __restrict__ h0, const float* __restrict__ emb,
    const int* __restrict__ tgt)
{
    int bid = blockIdx.x, tid = threadIdx.x;
    if (bid < PR_WOUT) {
        int i = (bid * 256 + tid) * 4;
        float4 v = *(const float4*)(Wout + i);
        split2(v.x, g_WoutH + i, g_WoutL + i);
        split2(v.y, g_WoutH + i + 1, g_WoutL + i + 1);
        split2(v.z, g_WoutH + i + 2, g_WoutL + i + 2);
        split2(v.w, g_WoutH + i + 3, g_WoutL + i + 3);
    } else if (bid < PR_WHH) {
        int i = ((bid - PR_WOUT) * 256 + tid) * 4;
        float4 v = *(const float4*)(W_hh + i);
        bf16* hh = g_BcatH + 512 * Hc + i;
        bf16* hl = g_BcatL + 512 * Hc + i;
        split2(v.x, hh, hl); split2(v.y, hh + 1, hl + 1);
        split2(v.z, hh + 2, hl + 2); split2(v.w, hh + 3, hl + 3);
    } else if (bid < PR_WAT) {
        int idx = (bid - PR_WHH) * 256 + tid;
        int k = idx >> 9, n = idx & 511;
        split2(Wa[idx], g_BcatH + n * Hc + k, g_BcatL + n * Hc + k);
    } else if (bid < PR_UAT) {
        int idx = (bid - PR_WAT) * 256 + tid;
        int k = idx >> 9, n = idx & 511;
        split2(Ua[idx], g_UaTH + n * Hc + k, g_UaTL + n * Hc + k);
    } else if (bid < PR_WIH) {
        int idx = (bid - PR_UAT) * 256 + tid;
        int r = idx >> 9, c = idx & 511;
        split2(W_ih[(size_t)r * 1024 + c], g_WihEH + idx, g_WihEL + idx);
        split2(W_ih[(size_t)r * 1024 + 512 + c], g_WihCH + idx, g_WihCL + idx);
    } else if (bid < PR_ENC) {
        int i = ((bid - PR_WIH) * 256 + tid) * 4;
        float4 v = *(const float4*)(enc + i);
        split2(v.x, g_encH + i, g_encL + i);
        split2(v.y, g_encH + i + 1, g_encL + i + 1);
        split2(v.z, g_encH + i + 2, g_encL + i + 2);
        split2(v.w, g_encH + i + 3, g_encL + i + 3);
    } else if (bid < PR_INIT) {
        int i = (bid - PR_ENC) * 256 + tid;
        if (i == 0) { g_barrier = 0u; g_tstep = 0u; }
        if (i < Bc * Tc) g_rowsum[i] = 0.f;
        float v = h0[i];
        g_h[i] = v;
        split2(v, g_hhi + i, g_hlo + i);
    } else {
        int idx = bid - PR_INIT;
        int t = idx >> 6, b = idx & 63;
        int tok = (t == 0) ? 0 : tgt[b * Tc + t - 1];
        size_t base = ((size_t)t * Bc + b) * Hc;
        const float* e = emb + (size_t)tok * Hc;
        for (int k = tid; k < Hc; k += 256)
            split2(e[k], g_xeH + base + k, g_xeL + base + k);
    }
}

__global__ void final_h_kernel(float* __restrict__ dst) {
    int i = blockIdx.x * 256 + threadIdx.x;
    if (i < Bc * Hc) dst[i] = g_h[i];
}

// ---------------- MMA building blocks -----------------------------------------
#define KC 16
#define LDApad 24
#define OFF_AH 0
#define OFF_AL (64 * LDApad)
#define OFF_BH (128 * LDApad)
#define OFF_BL (256 * LDApad)
#define STG_ELEMS (384 * LDApad)

#define MMA_BF16(c, a, b0_, b1_)                                           \
    asm volatile(                                                          \
        "mma.sync.aligned.m16n8k16.row.col.f32.bf16.bf16.f32 "             \
        "{%0,%1,%2,%3},{%4,%5,%6,%7},{%8,%9},{%0,%1,%2,%3};"               \
        : "+f"(c[0]), "+f"(c[1]), "+f"(c[2]), "+f"(c[3])                   \
        : "r"(a[0]), "r"(a[1]), "r"(a[2]), "r"(a[3]), "r"(b0_), "r"(b1_))

#define LDSM4(r, addr)                                                     \
    asm volatile("ldmatrix.sync.aligned.m8n8.x4.shared.b16 {%0,%1,%2,%3}, [%4];" \
        : "=r"(r[0]), "=r"(r[1]), "=r"(r[2]), "=r"(r[3]) : "r"(addr))

__device__ __forceinline__ void cpa16(uint32_t dst, const void* src) {
    asm volatile("cp.async.ca.shared.global [%0], [%1], 16;" :: "r"(dst), "l"(src));
}
__device__ __forceinline__ void cpa16_ef(uint32_t dst, const void* src, uint64_t pol) {
    asm volatile("cp.async.ca.shared.global.L2::cache_hint [%0], [%1], 16, %2;"
                 :: "r"(dst), "l"(src), "l"(pol));
}

// 64(M) x 128(N) tile, 2-stage cp.async pipeline, lda/ldb = 512, ldmatrix frags.
__device__ __forceinline__ void mma_tile(
    bf16* sm, const bf16* Ahi, const bf16* Alo,
    const bf16* Bhi, const bf16* Blo,
    const float* bias, float* out,
    int m0, int n0, int kb, int niters, size_t ldc, int nterms)
{
    uint32_t sb = (uint32_t)__cvta_generic_to_shared(sm);
    int tid = threadIdx.x, lane = tid & 31, wid = tid >> 5;
    int g = lane >> 2, t4 = lane & 3;
    int wy = wid & 3, wx = wid >> 2;

    int ac = tid & 127, arow = ac >> 1, ao8 = (ac & 1) * 8;
    const bf16* aptr = (tid < 128 ? Ahi : Alo) + (size_t)(m0 + arow) * 512 + ao8;
    uint32_t adst = sb + 2 * ((tid < 128 ? OFF_AH : OFF_AL) + arow * LDApad + ao8);
    int brow = tid >> 1, bo8 = (tid & 1) * 8;
    const bf16* bhp = Bhi + (size_t)(n0 + brow) * 512 + bo8;
    const bf16* blp = Blo + (size_t)(n0 + brow) * 512 + bo8;
    uint32_t bhd = sb + 2 * (OFF_BH + brow * LDApad + bo8);
    uint32_t bld = sb + 2 * (OFF_BL + brow * LDApad + bo8);

    int la = (wy * 16 + (lane & 15)) * LDApad + (lane >> 4) * 8;
    int nloc = (lane & 7) | ((lane & 16) >> 1);
    int kq2 = ((lane >> 3) & 1) * 8;
    int lb = (wx * 64 + nloc) * LDApad + kq2;

    float acc[8][4] = {};

    cpa16(adst, aptr + kb);
    cpa16(bhd, bhp + kb);
    cpa16(bld, blp + kb);
    asm volatile("cp.async.commit_group;");

    int st = 0;
    for (int it = 0; it < niters; it++) {
        if (it + 1 < niters) {
            int kn = kb + (it + 1) * KC;
            uint32_t so = (uint32_t)((st ^ 1) * STG_ELEMS * 2);
            cpa16(adst + so, aptr + kn);
            cpa16(bhd + so, bhp + kn);
            cpa16(bld + so, blp + kn);
            asm volatile("cp.async.commit_group;");
            asm volatile("cp.async.wait_group 1;");
        } else {
            asm volatile("cp.async.wait_group 0;");
        }
        __syncthreads();

        uint32_t stoff = (uint32_t)(st * STG_ELEMS * 2);
        uint32_t aH[4], aL[4];
        LDSM4(aH, sb + stoff + 2 * (OFF_AH + la));
        if (nterms == 3) LDSM4(aL, sb + stoff + 2 * (OFF_AL + la));
#pragma unroll
        for (int q = 0; q < 4; q++) {
            uint32_t bH[4], bL[4];
            LDSM4(bH, sb + stoff + 2 * (OFF_BH + lb + q * 16 * LDApad));
            LDSM4(bL, sb + stoff + 2 * (OFF_BL + lb + q * 16 * LDApad));
            MMA_BF16(acc[2 * q],     aH, bH[0], bH[1]);
            MMA_BF16(acc[2 * q + 1], aH, bH[2], bH[3]);
            MMA_BF16(acc[2 * q],     aH, bL[0], bL[1]);
            MMA_BF16(acc[2 * q + 1], aH, bL[2], bL[3]);
            if (nterms == 3) {
                MMA_BF16(acc[2 * q],     aL, bH[0], bH[1]);
                MMA_BF16(acc[2 * q + 1], aL, bH[2], bH[3]);
            }
        }
        __syncthreads();
        st ^= 1;
    }

    int mr0 = m0 + wy * 16 + g, mr1 = mr0 + 8;
    size_t ro0 = (size_t)mr0 * ldc, ro1 = (size_t)mr1 * ldc;
#pragma unroll
    for (int nf = 0; nf < 8; nf++) {
        int col = n0 + wx * 64 + nf * 8 + t4 * 2;
        float b0 = bias ? bias[col] : 0.f;
        float b1 = bias ? bias[col + 1] : 0.f;
        out[ro0 + col]     = acc[nf][0] + b0;
        out[ro0 + col + 1] = acc[nf][1] + b1;
        out[ro1 + col]     = acc[nf][2] + b0;
        out[ro1 + col + 1] = acc[nf][3] + b1;
    }
}

// ---------------- standalone MMA kernel (Uk, giE, encW) ----------------------
__global__ __launch_bounds__(256) void mma_nt_kernel(
    const bf16* __restrict__ Ahi, const bf16* __restrict__ Alo,
    const bf16* __restrict__ Bhi, const bf16* __restrict__ Blo,
    const float* __restrict__ bias, float* __restrict__ out,
    int Kcp, size_t ldc, int nterms)
{
    __shared__ __align__(16) bf16 sm[2 * STG_ELEMS];
    mma_tile(sm, Ahi, Alo, Bhi, Blo, bias, out,
             blockIdx.y * 64, blockIdx.x * 128, 0, Kcp / KC, ldc, nterms);
}

// ---------------- logits tile M=256 (2-term, scatter + rowsum atomics) -------
#define L2_AH 0
#define L2_BH (256 * LDApad)
#define L2_BL (384 * LDApad)
#define L2_STG (512 * LDApad)     // 24.6 KB per stage

__device__ __forceinline__ void logits_tile256(
    bf16* sm, const bf16* Ahi, const bf16* Bhi, const bf16* Blo,
    const float* bias, float* out, int m0, int n0)
{
    uint32_t sb = (uint32_t)__cvta_generic_to_shared(sm);
    int tid = threadIdx.x, lane = tid & 31, wid = tid >> 5;
    int g = lane >> 2, t4 = lane & 3;
    int wy = wid & 3, wx = wid >> 2;

    uint64_t pol;
    asm volatile("createpolicy.fractional.L2::evict_first.b64 %0, 1.0;" : "=l"(pol));

    int ar = tid >> 1, ao = (tid & 1) * 8;
    const bf16* ap0 = Ahi + (size_t)(m0 + ar) * 512 + ao;
    const bf16* ap1 = ap0 + (size_t)128 * 512;
    uint32_t ad0 = sb + 2 * (L2_AH + ar * LDApad + ao);
    uint32_t ad1 = ad0 + 2 * (128 * LDApad);
    const bf16* bhp = Bhi + (size_t)(n0 + ar) * 512 + ao;
    const bf16* blp = Blo + (size_t)(n0 + ar) * 512 + ao;
    uint32_t bhd = sb + 2 * (L2_BH + ar * LDApad + ao);
    uint32_t bld = sb + 2 * (L2_BL + ar * LDApad + ao);

    int la = (wy * 16 + (lane & 15)) * LDApad + (lane >> 4) * 8;
    int nloc = (lane & 7) | ((lane & 16) >> 1);
    int kq2 = ((lane >> 3) & 1) * 8;
    int lb = (wx * 64 + nloc) * LDApad + kq2;

    float acc[4][8][4] = {};

    cpa16_ef(ad0, ap0, pol);
    cpa16_ef(ad1, ap1, pol);
    cpa16_ef(bhd, bhp, pol);
    cpa16_ef(bld, blp, pol);
    asm volatile("cp.async.commit_group;");

    int st = 0;
    const int niters = Hc / KC;   // 32
    for (int it = 0; it < niters; it++) {
        if (it + 1 < niters) {
            int kn = (it + 1) * KC;
            uint32_t so = (uint32_t)((st ^ 1) * L2_STG * 2);
            cpa16_ef(ad0 + so, ap0 + kn, pol);
            cpa16_ef(ad1 + so, ap1 + kn, pol);
            cpa16_ef(bhd + so, bhp + kn, pol);
            cpa16_ef(bld + so, blp + kn, pol);
            asm volatile("cp.async.commit_group;");
            asm volatile("cp.async.wait_group 1;");
        } else {
            asm volatile("cp.async.wait_group 0;");
        }
        __syncthreads();

        uint32_t stoff = (uint32_t)(st * L2_STG * 2);
        uint32_t aH[4][4];
#pragma unroll
        for (int ms = 0; ms < 4; ms++)
            LDSM4(aH[ms], sb + stoff + 2 * (L2_AH + ms * 64 * LDApad + la));
#pragma unroll
        for (int q = 0; q < 4; q++) {
            uint32_t bH[4], bL[4];
            LDSM4(bH, sb + stoff + 2 * (L2_BH + lb + q * 16 * LDApad));
            LDSM4(bL, sb + stoff + 2 * (L2_BL + lb + q * 16 * LDApad));
#pragma unroll
            for (int ms = 0; ms < 4; ms++) {
                MMA_BF16(acc[ms][2 * q],     aH[ms], bH[0], bH[1]);
                MMA_BF16(acc[ms][2 * q + 1], aH[ms], bH[2], bH[3]);
                MMA_BF16(acc[ms][2 * q],     aH[ms], bL[0], bL[1]);
                MMA_BF16(acc[ms][2 * q + 1], aH[ms], bL[2], bL[3]);
            }
        }
        __syncthreads();
        st ^= 1;
    }

#pragma unroll
    for (int ms = 0; ms < 4; ms++) {
        int mr0 = m0 + ms * 64 + wy * 16 + g, mr1 = mr0 + 8;
        int r0 = (mr0 & 63) * Tc + (mr0 >> 6);   // output row ids (b*T + t)
        int r1 = (mr1 & 63) * Tc + (mr1 >> 6);
        size_t ro0 = (size_t)r0 * Vc, ro1 = (size_t)r1 * Vc;
        float es0 = 0.f, es1 = 0.f;
#pragma unroll
        for (int nf = 0; nf < 8; nf++) {
            int col = n0 + wx * 64 + nf * 8 + t4 * 2;
            float b0 = bias[col], b1 = bias[col + 1];
            float v00 = acc[ms][nf][0] + b0, v01 = acc[ms][nf][1] + b1;
            float v10 = acc[ms][nf][2] + b0, v11 = acc[ms][nf][3] + b1;
            out[ro0 + col]     = v00;
            out[ro0 + col + 1] = v01;
            out[ro1 + col]     = v10;
            out[ro1 + col + 1] = v11;
            es0 += fexp(v00) + fexp(v01);
            es1 += fexp(v10) + fexp(v11);
        }
        es0 += __shfl_xor_sync(0xffffffffu, es0, 1);
        es0 += __shfl_xor_sync(0xffffffffu, es0, 2);
        es1 += __shfl_xor_sync(0xffffffffu, es1, 1);
        es1 += __shfl_xor_sync(0xffffffffu, es1, 2);
        if (t4 == 0) {
            atomicAdd(&g_rowsum[r0], es0);
            atomicAdd(&g_rowsum[r1], es1);
        }
    }
}

// ---------------- megakernel: 2-phase loop (64 blocks) + overlapped logits ----
// 120KB dyn smem forces 1 block/SM: loop blocks own their SMs exclusively.
__global__ __launch_bounds__(256) void mega_kernel(
    const float* __restrict__ Va, const float* __restrict__ ba,
    const float* __restrict__ b_ih, const float* __restrict__ b_hh,
    const float* __restrict__ bout,
    float* __restrict__ att, float* __restrict__ logp)
{
    extern __shared__ __align__(16) bf16 sm[];
    int bid = blockIdx.x, tid = threadIdx.x;

    if (bid >= NBLK) {
        // ---------------- logits role (M=256 tiles) ----------------
        int job = bid - NBLK;
        int my = job / 250, nx = job % 250;   // m-major: unlocks pipeline vs loop
        unsigned int need = 4 * my + 4;       // tile covers t in [4my, 4my+3]
        if (tid == 0) {
            unsigned int v;
            for (;;) {
                asm volatile("ld.acquire.gpu.global.u32 %0, [%1];"
                             : "=r"(v) : "l"(&g_tstep) : "memory");
                if (v >= need) break;
                asm volatile("nanosleep.u32 4000;");
            }
        }
        __syncthreads();
        logits_tile256(sm, g_hallH, g_WoutH, g_WoutL, bout, logp, my * 256, nx * 128);
        return;
    }

    // ---------------- loop role: 2 phases per step ----------------
    int lane = tid & 31, warp = tid >> 5;
    unsigned int gen = 0;
    float* smf = (float*)sm;
    float* shwa = smf;          // 512
    float* sva  = smf + 512;    // 512
    float* sw   = smf + 1024;   // 128

#define GRID_BAR()                                                             \
    do {                                                                       \
        __syncthreads();                                                       \
        gen += NBLK;                                                           \
        if (tid == 0) {                                                        \
            asm volatile("red.release.gpu.global.add.u32 [%0], 1;"             \
                         :: "l"(&g_barrier) : "memory");                       \
            unsigned int v;                                                    \
            do {                                                               \
                asm volatile("ld.acquire.gpu.global.u32 %0, [%1];"             \
                             : "=r"(v) : "l"(&g_barrier) : "memory");          \
            } while (v < gen);                                                 \
        }                                                                      \
        __syncthreads();                                                       \
    } while (0)

    for (int t = 0; t < Tc; t++) {
        // -- phase 1: [hwa|gh] partials = h @ Bcat^T : 16 n-tiles x 4 K-splits
        {
            int n0 = (bid & 15) * 128, kz = bid >> 4;
            mma_tile(sm, g_hhi, g_hlo, g_BcatH, g_BcatL, nullptr,
                     g_A4 + (size_t)kz * Bc * 2048,
                     0, n0, kz * 128, 128 / KC, 2048, 3);
        }
        GRID_BAR();

        // -- phase 2: scores + softmax + att + giC(w @ encW) + gates ---------
        {
            int b = bid;
            for (int i = tid; i < Hc; i += 256) {
                float v = ba[i];
#pragma unroll
                for (int p = 0; p < 4; p++) v += g_A4[(size_t)p * Bc * 2048 + b * 2048 + i];
                shwa[i] = v;
                sva[i] = Va[i];
            }
            __syncthreads();
            // scores: 8 warps x 16 s
#pragma unroll 2
            for (int si = 0; si < 16; si++) {
                int s = warp * 16 + si;
                const float* uk = g_Uk + ((size_t)b * Sc + s) * Hc;
                float acc = 0.f;
#pragma unroll
                for (int j = 0; j < 4; j++) {
                    int k = j * 128 + lane * 4;
                    float4 u  = *(const float4*)(uk + k);
                    float4 wv = *(const float4*)(shwa + k);
                    float4 vv = *(const float4*)(sva + k);
                    acc += fast_tanh(wv.x + u.x) * vv.x + fast_tanh(wv.y + u.y) * vv.y
                         + fast_tanh(wv.z + u.z) * vv.z + fast_tanh(wv.w + u.w) * vv.w;
                }
#pragma unroll
                for (int o = 16; o; o >>= 1) acc += __shfl_xor_sync(0xffffffffu, acc, o);
                if (!lane) sw[s] = acc;    // bv cancels in softmax
            }
            __syncthreads();
            // softmax over S=128 in warp 0
            if (warp == 0) {
                float v0 = sw[lane], v1 = sw[lane + 32], v2 = sw[lane + 64], v3 = sw[lane + 96];
                float m = fmaxf(fmaxf(v0, v1), fmaxf(v2, v3));
#pragma unroll
                for (int o = 16; o; o >>= 1) m = fmaxf(m, __shfl_xor_sync(0xffffffffu, m, o));
                float e0 = expf(v0 - m), e1 = expf(v1 - m), e2 = expf(v2 - m), e3 = expf(v3 - m);
                float s = e0 + e1 + e2 + e3;
#pragma unroll
                for (int o = 16; o; o >>= 1) s += __shfl_xor_sync(0xffffffffu, s, o);
                float inv = 1.0f / s;
                sw[lane] = e0 * inv; sw[lane + 32] = e1 * inv;
                sw[lane + 64] = e2 * inv; sw[lane + 96] = e3 * inv;
            }
            __syncthreads();
            if (tid < Sc) att[((size_t)b * Tc + t) * Sc + tid] = sw[tid];

            // giC = w @ encW[b]  fused with gates (2 j per thread)
            size_t r = (size_t)t * Bc + b;
            const float* ew = g_encW + (size_t)b * Sc * 1536;
#pragma unroll
            for (int jj = 0; jj < 2; jj++) {
                int j = tid + jj * 256;
                float c0 = 0.f, c1 = 0.f, c2 = 0.f;
#pragma unroll 4
                for (int s = 0; s < Sc; s++) {
                    float w = sw[s];
                    const float* row = ew + s * 1536;
                    c0 = fmaf(w, row[j], c0);
                    c1 = fmaf(w, row[Hc + j], c1);
                    c2 = fmaf(w, row[2 * Hc + j], c2);
                }
                float ghr = 0.f, ghz = 0.f, ghn = 0.f;
#pragma unroll
                for (int p = 0; p < 4; p++) {
                    const float* A4 = g_A4 + (size_t)p * Bc * 2048 + b * 2048 + 512;
                    ghr += A4[j]; ghz += A4[Hc + j]; ghn += A4[2 * Hc + j];
                }
                const float* giE = g_giE + r * (3 * Hc);
                float rr = sigm(giE[j] + c0 + b_ih[j] + ghr + b_hh[j]);
                float z  = sigm(giE[Hc + j] + c1 + b_ih[Hc + j] + ghz + b_hh[Hc + j]);
                float n  = tanhf(giE[2 * Hc + j] + c2 + b_ih[2 * Hc + j]
                                 + rr * (ghn + b_hh[2 * Hc + j]));
                float hp = g_h[b * Hc + j];
                float hn = (1.0f - z) * n + z * hp;
                g_h[b * Hc + j] = hn;
                split2(hn, g_hhi + b * Hc + j, g_hlo + b * Hc + j);
                g_hallH[r * Hc + j] = __float2bfloat16(hn);
            }
        }
        GRID_BAR();

        // publish progress for logits blocks
        if (bid == 0 && tid == 0) {
            unsigned int tv = (unsigned int)(t + 1);
            asm volatile("st.release.gpu.global.u32 [%0], %1;"
                         :: "l"(&g_tstep), "r"(tv) : "memory");
        }
    }
#undef GRID_BAR
}

// ---------------- subtract log-sum per row ------------------------------------
__global__ __launch_bounds__(512) void sub_kernel(float* __restrict__ base)
{
    int r = blockIdx.x;
    float ls = logf(g_rowsum[r]);
    float4* row = (float4*)(base + (size_t)r * Vc);
    const int NV4 = Vc / 4;   // 8000
    for (int v = threadIdx.x; v < NV4; v += 512) {
        float4 x = row[v];
        x.x -= ls; x.y -= ls; x.z -= ls; x.w -= ls;
        row[v] = x;
    }
}

// ---------------- launch ----------------
extern "C" void kernel_launch(void* const* d_in, const int* in_sizes, int n_in,
                              void* d_out, int out_size)
{
    const float* enc  = (const float*)d_in[0];
    const float* h0   = (const float*)d_in[1];
    const int*   tgt  = (const int*)d_in[2];
    const float* emb  = (const float*)d_in[3];
    const float* Wa   = (const float*)d_in[4];
    const float* ba   = (const float*)d_in[5];
    const float* Ua   = (const float*)d_in[6];
    const float* bu   = (const float*)d_in[7];
    const float* Va   = (const float*)d_in[8];
    /* d_in[9] = bv : cancels inside softmax, never observable */
    const float* W_ih = (const float*)d_in[10];
    const float* W_hh = (const float*)d_in[11];
    const float* b_ih = (const float*)d_in[12];
    const float* b_hh = (const float*)d_in[13];
    const float* Wout = (const float*)d_in[14];
    const float* bout = (const float*)d_in[15];

    float* out  = (float*)d_out;
    float* logp = out;                                    // [B,T,V]
    float* hf   = out + (size_t)Bc * Tc * Vc;             // [1,B,H]
    float* att  = hf + (size_t)Bc * Hc;                   // [B,T,S]

    void *p_encH, *p_encL, *p_UaTH, *p_UaTL, *p_xeH, *p_xeL;
    void *p_WihEH, *p_WihEL, *p_WihCH, *p_WihCL, *p_Uk, *p_giE, *p_encW;
    cudaGetSymbolAddress(&p_encH, g_encH);   cudaGetSymbolAddress(&p_encL, g_encL);
    cudaGetSymbolAddress(&p_UaTH, g_UaTH);   cudaGetSymbolAddress(&p_UaTL, g_UaTL);
    cudaGetSymbolAddress(&p_xeH, g_xeH);     cudaGetSymbolAddress(&p_xeL, g_xeL);
    cudaGetSymbolAddress(&p_WihEH, g_WihEH); cudaGetSymbolAddress(&p_WihEL, g_WihEL);
    cudaGetSymbolAddress(&p_WihCH, g_WihCH); cudaGetSymbolAddress(&p_WihCL, g_WihCL);
    cudaGetSymbolAddress(&p_Uk, g_Uk);       cudaGetSymbolAddress(&p_giE, g_giE);
    cudaGetSymbolAddress(&p_encW, g_encW);

    // launch 1: ALL setup work fused
    prep_kernel<<<PR_XE, 256>>>(Wout, W_hh, Wa, Ua, W_ih, enc, h0, emb, tgt);

    // launch 2: Uk = enc @ UaT^T + bu : M=8192, N=512, K=512
    mma_nt_kernel<<<dim3(4, 128), 256>>>((bf16*)p_encH, (bf16*)p_encL,
                                         (bf16*)p_UaTH, (bf16*)p_UaTL,
                                         bu, (float*)p_Uk, Hc, (size_t)Hc, 3);
    // launch 3: giE = xe @ WihE^T : M=4096, N=1536, K=512
    mma_nt_kernel<<<dim3(12, 64), 256>>>((bf16*)p_xeH, (bf16*)p_xeL,
                                         (bf16*)p_WihEH, (bf16*)p_WihEL,
                                         nullptr, (float*)p_giE, Hc, (size_t)(3 * Hc), 3);
    // launch 4: encW = enc @ WihC^T : M=8192, N=1536, K=512  (moves giC GEMM
    // out of the recurrent loop via linearity: giC_t = w_t @ encW)
    mma_nt_kernel<<<dim3(12, 128), 256>>>((bf16*)p_encH, (bf16*)p_encL,
                                          (bf16*)p_WihCH, (bf16*)p_WihCL,
                                          nullptr, (float*)p_encW, Hc, (size_t)1536, 3);

    // launch 5: 2-phase loop + overlapped logits (1 block/SM via 120KB smem)
    cudaFuncSetAttribute(mega_kernel, cudaFuncAttributeMaxDynamicSharedMemorySize,
                         MEGA_SMEM);
    mega_kernel<<<NBLK + NLOGITS, 256, MEGA_SMEM>>>(Va, ba, b_ih, b_hh, bout,
                                                    att, logp);

    // launch 6: log_softmax finalize
    sub_kernel<<<Bc * Tc, 512>>>(logp);

    // launch 7: final hidden state
    final_h_kernel<<<(Bc * Hc + 255) / 256, 256>>>(hf);
}

// round 15
// speedup vs baseline: 1.6478x; 1.6478x over previous
#include <cuda_runtime.h>
#include <cuda_bf16.h>
#include <math.h>
#include <stdint.h>

#define Bc 64
#define Sc 128
#define Tc 64
#define Hc 512
#define Vc 32000
#define NBLK 64
#define NLOGITS (16 * 250)   // 16 m-tiles (M=256) x 250 n-tiles
#define MEGA_SMEM (120 * 1024)

typedef __nv_bfloat16 bf16;

// ---------------- scratch (device globals: no allocs allowed) ----------------
__device__ __align__(16) float g_Uk[(size_t)Bc * Sc * Hc];       // 16 MB
__device__ __align__(16) float g_h[Bc * Hc];
__device__ __align__(16) bf16  g_hhi[Bc * Hc], g_hlo[Bc * Hc];
__device__ __align__(16) float g_A4[4 * Bc * 2048];              // K-split partials [hwa|gh]
__device__ __align__(16) float g_giC4[4 * Bc * 1536];            // K-split partials giC
__device__ __align__(16) float g_giE[(size_t)Tc * Bc * 3 * Hc];  // 25 MB
__device__ __align__(16) bf16  g_xeH[(size_t)Tc * Bc * Hc], g_xeL[(size_t)Tc * Bc * Hc];
__device__ __align__(16) bf16  g_ctxH[Bc * Hc], g_ctxL[Bc * Hc];
__device__ __align__(16) bf16  g_hallH[(size_t)Tc * Bc * Hc];
__device__ __align__(16) bf16  g_WoutH[(size_t)Vc * Hc], g_WoutL[(size_t)Vc * Hc];
__device__ __align__(16) bf16  g_BcatH[2048 * Hc], g_BcatL[2048 * Hc]; // [WaT|W_hh]
__device__ __align__(16) bf16  g_WihEH[3 * Hc * Hc], g_WihEL[3 * Hc * Hc];
__device__ __align__(16) bf16  g_WihCH[3 * Hc * Hc], g_WihCL[3 * Hc * Hc];
__device__ __align__(16) bf16  g_UaTH[Hc * Hc], g_UaTL[Hc * Hc];
__device__ __align__(16) bf16  g_encH[(size_t)Bc * Sc * Hc], g_encL[(size_t)Bc * Sc * Hc];
__device__ float g_rowsum[Bc * Tc];   // per-output-row sum of exp(logits)
__device__ unsigned int g_barrier;
__device__ unsigned int g_tstep;

__device__ __forceinline__ float sigm(float x) { return 1.0f / (1.0f + expf(-x)); }
__device__ __forceinline__ float fast_tanh(float x) {
    float y; asm("tanh.approx.f32 %0, %1;" : "=f"(y) : "f"(x)); return y;
}
__device__ __forceinline__ void split2(float x, bf16* hi, bf16* lo) {
    bf16 h = __float2bfloat16(x);
    *hi = h;
    *lo = __float2bfloat16(x - __bfloat162float(h));
}
// vectorized: split 4 consecutive floats, store hi/lo as two bf16x2 each
__device__ __forceinline__ void split4(float4 v, bf16* hi, bf16* lo) {
    bf16 h0 = __float2bfloat16(v.x), h1 = __float2bfloat16(v.y);
    bf16 h2 = __float2bfloat16(v.z), h3 = __float2bfloat16(v.w);
    bf16 l0 = __float2bfloat16(v.x - __bfloat162float(h0));
    bf16 l1 = __float2bfloat16(v.y - __bfloat162float(h1));
    bf16 l2 = __float2bfloat16(v.z - __bfloat162float(h2));
    bf16 l3 = __float2bfloat16(v.w - __bfloat162float(h3));
    __nv_bfloat162* H = (__nv_bfloat162*)hi;
    __nv_bfloat162* L = (__nv_bfloat162*)lo;
    H[0] = __halves2bfloat162(h0, h1);
    H[1] = __halves2bfloat162(h2, h3);
    L[0] = __halves2bfloat162(l0, l1);
    L[1] = __halves2bfloat162(l2, l3);
}
// FMA-pipe exp (avoids MUFU EX2): 2^(x*log2e) via deg-5 poly.
__device__ __forceinline__ float fexp(float x) {
    float y = x * 1.44269504f;
    y = fminf(fmaxf(y, -60.f), 60.f);
    int i = __float2int_rn(y);
    float f = y - (float)i;
    float p = 1.3333558e-3f;
    p = fmaf(p, f, 9.618129e-3f);
    p = fmaf(p, f, 5.550411e-2f);
    p = fmaf(p, f, 2.402265e-1f);
    p = fmaf(p, f, 6.931472e-1f);
    p = fmaf(p, f, 1.0f);
    return p * __int_as_float((i + 127) << 23);
}

// ---------------- ONE fused prep kernel (all conversions + init + gather) ----
#define PR_WOUT   16000                 // Wout split
#define PR_WHH    (PR_WOUT + 768)       // W_hh -> Bcat tail
#define PR_WAT    (PR_WHH + 1024)       // Wa^T -> Bcat head
#define PR_UAT    (PR_WAT + 1024)       // Ua^T
#define PR_WIH    (PR_UAT + 3072)       // Wih E/C split
#define PR_ENC    (PR_WIH + 4096)       // enc split
#define PR_INIT   (PR_ENC + 128)        // h init + flags
#define PR_XE     (PR_INIT + 4096)      // emb gather

__global__ __launch_bounds__(256) void prep_kernel(
    const float* __restrict__ Wout, const float* __restrict__ W_hh,
    const float* __restrict__ Wa, const float* __restrict__ Ua,
    const float* __restrict__ W_ih, const float* __restrict__ enc,
    const float* __restrict__ h0, const float* __restrict__ emb,
    const int* __restrict__ tgt)
{
    int bid = blockIdx.x, tid = threadIdx.x;
    if (bid < PR_WOUT) {
        int i = (bid * 256 + tid) * 4;
        split4(*(const float4*)(Wout + i), g_WoutH + i, g_WoutL + i);
    } else if (bid < PR_WHH) {
        int i = ((bid - PR_WOUT) * 256 + tid) * 4;
        split4(*(const float4*)(W_hh + i), g_BcatH + 512 * Hc + i, g_BcatL + 512 * Hc + i);
    } else if (bid < PR_WAT) {
        int idx = (bid - PR_WHH) * 256 + tid;
        int k = idx >> 9, n = idx & 511;
        split2(Wa[idx], g_BcatH + n * Hc + k, g_BcatL + n * Hc + k);
    } else if (bid < PR_UAT) {
        int idx = (bid - PR_WAT) * 256 + tid;
        int k = idx >> 9, n = idx & 511;
        split2(Ua[idx], g_UaTH + n * Hc + k, g_UaTL + n * Hc + k);
    } else if (bid < PR_WIH) {
        int idx = (bid - PR_UAT) * 256 + tid;
        int r = idx >> 9, c = idx & 511;
        split2(W_ih[(size_t)r * 1024 + c], g_WihEH + idx, g_WihEL + idx);
        split2(W_ih[(size_t)r * 1024 + 512 + c], g_WihCH + idx, g_WihCL + idx);
    } else if (bid < PR_ENC) {
        int i = ((bid - PR_WIH) * 256 + tid) * 4;
        split4(*(const float4*)(enc + i), g_encH + i, g_encL + i);
    } else if (bid < PR_INIT) {
        int i = (bid - PR_ENC) * 256 + tid;
        if (i == 0) { g_barrier = 0u; g_tstep = 0u; }
        if (i < Bc * Tc) g_rowsum[i] = 0.f;
        float v = h0[i];
        g_h[i] = v;
        split2(v, g_hhi + i, g_hlo + i);
    } else {
        int idx = bid - PR_INIT;
        int t = idx >> 6, b = idx & 63;
        int tok = (t == 0) ? 0 : tgt[b * Tc + t - 1];
        size_t base = ((size_t)t * Bc + b) * Hc;
        const float* e = emb + (size_t)tok * Hc;
        for (int k = tid; k < Hc; k += 256)
            split2(e[k], g_xeH + base + k, g_xeL + base + k);
    }
}

__global__ void final_h_kernel(float* __restrict__ dst) {
    int i = blockIdx.x * 256 + threadIdx.x;
    if (i < Bc * Hc) dst[i] = g_h[i];
}

// ---------------- MMA building blocks -----------------------------------------
#define MMA_BF16(c, a, b0_, b1_)                                           \
    asm volatile(                                                          \
        "mma.sync.aligned.m16n8k16.row.col.f32.bf16.bf16.f32 "             \
        "{%0,%1,%2,%3},{%4,%5,%6,%7},{%8,%9},{%0,%1,%2,%3};"               \
        : "+f"(c[0]), "+f"(c[1]), "+f"(c[2]), "+f"(c[3])                   \
        : "r"(a[0]), "r"(a[1]), "r"(a[2]), "r"(a[3]), "r"(b0_), "r"(b1_))

#define LDSM4(r, addr)                                                     \
    asm volatile("ldmatrix.sync.aligned.m8n8.x4.shared.b16 {%0,%1,%2,%3}, [%4];" \
        : "=r"(r[0]), "=r"(r[1]), "=r"(r[2]), "=r"(r[3]) : "r"(addr))

__device__ __forceinline__ void cpa16(uint32_t dst, const void* src) {
    asm volatile("cp.async.ca.shared.global [%0], [%1], 16;" :: "r"(dst), "l"(src));
}
__device__ __forceinline__ void cpa16_ef(uint32_t dst, const void* src, uint64_t pol) {
    asm volatile("cp.async.ca.shared.global.L2::cache_hint [%0], [%1], 16, %2;"
                 :: "r"(dst), "l"(src), "l"(pol));
}

// ---- KC=32 tile for loop/setup GEMMs (halves sync count vs KC=16) ----
// pad 40: ldmatrix 8-row stride 80B -> banks {0,20,8,28,16,4,24,12}, conflict-free
#define KC2 32
#define PAD2 40
#define O2_AH 0
#define O2_AL (64 * PAD2)
#define O2_BH (128 * PAD2)
#define O2_BL (256 * PAD2)
#define STG2  (384 * PAD2)     // 15360 elems = 30.7 KB per stage

__device__ __forceinline__ void mma_tile(
    bf16* sm, const bf16* Ahi, const bf16* Alo,
    const bf16* Bhi, const bf16* Blo,
    const float* bias, float* out,
    int m0, int n0, int kb, int niters, size_t ldc, int nterms)
{
    uint32_t sb = (uint32_t)__cvta_generic_to_shared(sm);
    int tid = threadIdx.x, lane = tid & 31, wid = tid >> 5;
    int g = lane >> 2, t4 = lane & 3;
    int wy = wid & 3, wx = wid >> 2;

    // cp.async assignments: A 64x32 (256 chunks each hi/lo), B 128x32 (512 each)
    int arow = tid >> 2, ac8 = (tid & 3) * 8;
    const bf16* ahp = Ahi + (size_t)(m0 + arow) * 512 + ac8;
    const bf16* alp = Alo + (size_t)(m0 + arow) * 512 + ac8;
    uint32_t ahd = sb + 2 * (O2_AH + arow * PAD2 + ac8);
    uint32_t ald = sb + 2 * (O2_AL + arow * PAD2 + ac8);
    int b0r = tid >> 2, b1r = 64 + (tid >> 2), bc8 = (tid & 3) * 8;
    const bf16* bh0 = Bhi + (size_t)(n0 + b0r) * 512 + bc8;
    const bf16* bh1 = Bhi + (size_t)(n0 + b1r) * 512 + bc8;
    const bf16* bl0 = Blo + (size_t)(n0 + b0r) * 512 + bc8;
    const bf16* bl1 = Blo + (size_t)(n0 + b1r) * 512 + bc8;
    uint32_t bh0d = sb + 2 * (O2_BH + b0r * PAD2 + bc8);
    uint32_t bh1d = sb + 2 * (O2_BH + b1r * PAD2 + bc8);
    uint32_t bl0d = sb + 2 * (O2_BL + b0r * PAD2 + bc8);
    uint32_t bl1d = sb + 2 * (O2_BL + b1r * PAD2 + bc8);

    int la = (wy * 16 + (lane & 15)) * PAD2 + (lane >> 4) * 8;
    int nloc = (lane & 7) | ((lane & 16) >> 1);
    int kq2 = ((lane >> 3) & 1) * 8;
    int lb = (wx * 64 + nloc) * PAD2 + kq2;

    float acc[8][4] = {};

    cpa16(ahd, ahp + kb);
    if (nterms == 3) cpa16(ald, alp + kb);
    cpa16(bh0d, bh0 + kb);
    cpa16(bh1d, bh1 + kb);
    cpa16(bl0d, bl0 + kb);
    cpa16(bl1d, bl1 + kb);
    asm volatile("cp.async.commit_group;");

    int st = 0;
    for (int it = 0; it < niters; it++) {
        if (it + 1 < niters) {
            int kn = kb + (it + 1) * KC2;
            uint32_t so = (uint32_t)((st ^ 1) * STG2 * 2);
            cpa16(ahd + so, ahp + kn);
            if (nterms == 3) cpa16(ald + so, alp + kn);
            cpa16(bh0d + so, bh0 + kn);
            cpa16(bh1d + so, bh1 + kn);
            cpa16(bl0d + so, bl0 + kn);
            cpa16(bl1d + so, bl1 + kn);
            asm volatile("cp.async.commit_group;");
            asm volatile("cp.async.wait_group 1;");
        } else {
            asm volatile("cp.async.wait_group 0;");
        }
        __syncthreads();

        uint32_t stoff = (uint32_t)(st * STG2 * 2);
#pragma unroll
        for (int kf = 0; kf < 2; kf++) {
            int ko = kf * 16;
            uint32_t aH[4], aL[4];
            LDSM4(aH, sb + stoff + 2 * (O2_AH + la + ko));
            if (nterms == 3) LDSM4(aL, sb + stoff + 2 * (O2_AL + la + ko));
#pragma unroll
            for (int q = 0; q < 4; q++) {
                uint32_t bH[4], bL[4];
                LDSM4(bH, sb + stoff + 2 * (O2_BH + lb + q * 16 * PAD2 + ko));
                LDSM4(bL, sb + stoff + 2 * (O2_BL + lb + q * 16 * PAD2 + ko));
                MMA_BF16(acc[2 * q],     aH, bH[0], bH[1]);
                MMA_BF16(acc[2 * q + 1], aH, bH[2], bH[3]);
                MMA_BF16(acc[2 * q],     aH, bL[0], bL[1]);
                MMA_BF16(acc[2 * q + 1], aH, bL[2], bL[3]);
                if (nterms == 3) {
                    MMA_BF16(acc[2 * q],     aL, bH[0], bH[1]);
                    MMA_BF16(acc[2 * q + 1], aL, bH[2], bH[3]);
                }
            }
        }
        __syncthreads();
        st ^= 1;
    }

    int mr0 = m0 + wy * 16 + g, mr1 = mr0 + 8;
    size_t ro0 = (size_t)mr0 * ldc, ro1 = (size_t)mr1 * ldc;
#pragma unroll
    for (int nf = 0; nf < 8; nf++) {
        int col = n0 + wx * 64 + nf * 8 + t4 * 2;
        float b0 = bias ? bias[col] : 0.f;
        float b1 = bias ? bias[col + 1] : 0.f;
        out[ro0 + col]     = acc[nf][0] + b0;
        out[ro0 + col + 1] = acc[nf][1] + b1;
        out[ro1 + col]     = acc[nf][2] + b0;
        out[ro1 + col + 1] = acc[nf][3] + b1;
    }
}

// ---------------- standalone MMA kernel (Uk, giE) — dynamic smem -------------
__global__ __launch_bounds__(256) void mma_nt_kernel(
    const bf16* __restrict__ Ahi, const bf16* __restrict__ Alo,
    const bf16* __restrict__ Bhi, const bf16* __restrict__ Blo,
    const float* __restrict__ bias, float* __restrict__ out,
    int Kcp, size_t ldc, int nterms)
{
    extern __shared__ __align__(16) bf16 smd[];
    mma_tile(smd, Ahi, Alo, Bhi, Blo, bias, out,
             blockIdx.y * 64, blockIdx.x * 128, 0, Kcp / KC2, ldc, nterms);
}

// ---------------- logits tile M=256 (KC=16, pad 24 — unchanged from R13) -----
#define KC 16
#define LDApad 24
#define L2_AH 0
#define L2_BH (256 * LDApad)
#define L2_BL (384 * LDApad)
#define L2_STG (512 * LDApad)     // 24.6 KB per stage

__device__ __forceinline__ void logits_tile256(
    bf16* sm, const bf16* Ahi, const bf16* Bhi, const bf16* Blo,
    const float* bias, float* out, int m0, int n0)
{
    uint32_t sb = (uint32_t)__cvta_generic_to_shared(sm);
    int tid = threadIdx.x, lane = tid & 31, wid = tid >> 5;
    int g = lane >> 2, t4 = lane & 3;
    int wy = wid & 3, wx = wid >> 2;

    uint64_t pol;
    asm volatile("createpolicy.fractional.L2::evict_first.b64 %0, 1.0;" : "=l"(pol));

    int ar = tid >> 1, ao = (tid & 1) * 8;
    const bf16* ap0 = Ahi + (size_t)(m0 + ar) * 512 + ao;
    const bf16* ap1 = ap0 + (size_t)128 * 512;
    uint32_t ad0 = sb + 2 * (L2_AH + ar * LDApad + ao);
    uint32_t ad1 = ad0 + 2 * (128 * LDApad);
    const bf16* bhp = Bhi + (size_t)(n0 + ar) * 512 + ao;
    const bf16* blp = Blo + (size_t)(n0 + ar) * 512 + ao;
    uint32_t bhd = sb + 2 * (L2_BH + ar * LDApad + ao);
    uint32_t bld = sb + 2 * (L2_BL + ar * LDApad + ao);

    int la = (wy * 16 + (lane & 15)) * LDApad + (lane >> 4) * 8;
    int nloc = (lane & 7) | ((lane & 16) >> 1);
    int kq2 = ((lane >> 3) & 1) * 8;
    int lb = (wx * 64 + nloc) * LDApad + kq2;

    float acc[4][8][4] = {};

    cpa16_ef(ad0, ap0, pol);
    cpa16_ef(ad1, ap1, pol);
    cpa16_ef(bhd, bhp, pol);
    cpa16_ef(bld, blp, pol);
    asm volatile("cp.async.commit_group;");

    int st = 0;
    const int niters = Hc / KC;   // 32
    for (int it = 0; it < niters; it++) {
        if (it + 1 < niters) {
            int kn = (it + 1) * KC;
            uint32_t so = (uint32_t)((st ^ 1) * L2_STG * 2);
            cpa16_ef(ad0 + so, ap0 + kn, pol);
            cpa16_ef(ad1 + so, ap1 + kn, pol);
            cpa16_ef(bhd + so, bhp + kn, pol);
            cpa16_ef(bld + so, blp + kn, pol);
            asm volatile("cp.async.commit_group;");
            asm volatile("cp.async.wait_group 1;");
        } else {
            asm volatile("cp.async.wait_group 0;");
        }
        __syncthreads();

        uint32_t stoff = (uint32_t)(st * L2_STG * 2);
        uint32_t aH[4][4];
#pragma unroll
        for (int ms = 0; ms < 4; ms++)
            LDSM4(aH[ms], sb + stoff + 2 * (L2_AH + ms * 64 * LDApad + la));
#pragma unroll
        for (int q = 0; q < 4; q++) {
            uint32_t bH[4], bL[4];
            LDSM4(bH, sb + stoff + 2 * (L2_BH + lb + q * 16 * LDApad));
            LDSM4(bL, sb + stoff + 2 * (L2_BL + lb + q * 16 * LDApad));
#pragma unroll
            for (int ms = 0; ms < 4; ms++) {
                MMA_BF16(acc[ms][2 * q],     aH[ms], bH[0], bH[1]);
                MMA_BF16(acc[ms][2 * q + 1], aH[ms], bH[2], bH[3]);
                MMA_BF16(acc[ms][2 * q],     aH[ms], bL[0], bL[1]);
                MMA_BF16(acc[ms][2 * q + 1], aH[ms], bL[2], bL[3]);
            }
        }
        __syncthreads();
        st ^= 1;
    }

#pragma unroll
    for (int ms = 0; ms < 4; ms++) {
        int mr0 = m0 + ms * 64 + wy * 16 + g, mr1 = mr0 + 8;
        int r0 = (mr0 & 63) * Tc + (mr0 >> 6);   // output row ids (b*T + t)
        int r1 = (mr1 & 63) * Tc + (mr1 >> 6);
        size_t ro0 = (size_t)r0 * Vc, ro1 = (size_t)r1 * Vc;
        float es0 = 0.f, es1 = 0.f;
#pragma unroll
        for (int nf = 0; nf < 8; nf++) {
            int col = n0 + wx * 64 + nf * 8 + t4 * 2;
            float b0 = bias[col], b1 = bias[col + 1];
            float v00 = acc[ms][nf][0] + b0, v01 = acc[ms][nf][1] + b1;
            float v10 = acc[ms][nf][2] + b0, v11 = acc[ms][nf][3] + b1;
            out[ro0 + col]     = v00;
            out[ro0 + col + 1] = v01;
            out[ro1 + col]     = v10;
            out[ro1 + col + 1] = v11;
            es0 += fexp(v00) + fexp(v01);
            es1 += fexp(v10) + fexp(v11);
        }
        es0 += __shfl_xor_sync(0xffffffffu, es0, 1);
        es0 += __shfl_xor_sync(0xffffffffu, es0, 2);
        es1 += __shfl_xor_sync(0xffffffffu, es1, 1);
        es1 += __shfl_xor_sync(0xffffffffu, es1, 2);
        if (t4 == 0) {
            atomicAdd(&g_rowsum[r0], es0);
            atomicAdd(&g_rowsum[r1], es1);
        }
    }
}

// ---------------- megakernel: R13 loop (64 blocks, isolated) + logits ---------
__global__ __launch_bounds__(256) void mega_kernel(
    const float* __restrict__ enc, const float* __restrict__ Va,
    const float* __restrict__ ba, const float* __restrict__ b_ih,
    const float* __restrict__ b_hh, const float* __restrict__ bout,
    float* __restrict__ att, float* __restrict__ logp)
{
    extern __shared__ __align__(16) bf16 sm[];
    int bid = blockIdx.x, tid = threadIdx.x;

    if (bid >= NBLK) {
        // ---------------- logits role (M=256 tiles) ----------------
        int job = bid - NBLK;
        int my = job / 250, nx = job % 250;
        unsigned int need = 4 * my + 4;
        if (tid == 0) {
            unsigned int v;
            for (;;) {
                asm volatile("ld.acquire.gpu.global.u32 %0, [%1];"
                             : "=r"(v) : "l"(&g_tstep) : "memory");
                if (v >= need) break;
                asm volatile("nanosleep.u32 4000;");
            }
        }
        __syncthreads();
        logits_tile256(sm, g_hallH, g_WoutH, g_WoutL, bout, logp, my * 256, nx * 128);
        return;
    }

    // ---------------- loop role (R13 structure, KC=32 GEMM phases) ------------
    int lane = tid & 31, warp = tid >> 5;
    unsigned int gen = 0;
    float* smf = (float*)sm;
    float* shwa = smf;          // 512
    float* sva  = smf + 512;    // 512
    float* sw   = smf + 1024;   // 128

#define GRID_BAR()                                                             \
    do {                                                                       \
        __syncthreads();                                                       \
        gen += NBLK;                                                           \
        if (tid == 0) {                                                        \
            asm volatile("red.release.gpu.global.add.u32 [%0], 1;"             \
                         :: "l"(&g_barrier) : "memory");                       \
            unsigned int v;                                                    \
            do {                                                               \
                asm volatile("ld.acquire.gpu.global.u32 %0, [%1];"             \
                             : "=r"(v) : "l"(&g_barrier) : "memory");          \
            } while (v < gen);                                                 \
        }                                                                      \
        __syncthreads();                                                       \
    } while (0)

    for (int t = 0; t < Tc; t++) {
        // -- phase 1: [hwa|gh] partials = h @ Bcat^T : 16 n-tiles x 4 K-splits
        {
            int n0 = (bid & 15) * 128, kz = bid >> 4;
            mma_tile(sm, g_hhi, g_hlo, g_BcatH, g_BcatL, nullptr,
                     g_A4 + (size_t)kz * Bc * 2048,
                     0, n0, kz * 128, 128 / KC2, 2048, 3);
        }
        GRID_BAR();

        // -- phase 2: fused scores + softmax + ctx (block = batch row) --------
        {
            int b = bid;
            for (int i = tid; i < Hc; i += 256) {
                float v = ba[i];
#pragma unroll
                for (int p = 0; p < 4; p++) v += g_A4[(size_t)p * Bc * 2048 + b * 2048 + i];
                shwa[i] = v;
                sva[i] = Va[i];
            }
            __syncthreads();
#pragma unroll 2
            for (int si = 0; si < 16; si++) {
                int s = warp * 16 + si;
                const float* uk = g_Uk + ((size_t)b * Sc + s) * Hc;
                float acc = 0.f;
#pragma unroll
                for (int j = 0; j < 4; j++) {
                    int k = j * 128 + lane * 4;
                    float4 u  = *(const float4*)(uk + k);
                    float4 wv = *(const float4*)(shwa + k);
                    float4 vv = *(const float4*)(sva + k);
                    acc += fast_tanh(wv.x + u.x) * vv.x + fast_tanh(wv.y + u.y) * vv.y
                         + fast_tanh(wv.z + u.z) * vv.z + fast_tanh(wv.w + u.w) * vv.w;
                }
#pragma unroll
                for (int o = 16; o; o >>= 1) acc += __shfl_xor_sync(0xffffffffu, acc, o);
                if (!lane) sw[s] = acc;    // bv cancels in softmax
            }
            __syncthreads();
            if (warp == 0) {
                float v0 = sw[lane], v1 = sw[lane + 32], v2 = sw[lane + 64], v3 = sw[lane + 96];
                float m = fmaxf(fmaxf(v0, v1), fmaxf(v2, v3));
#pragma unroll
                for (int o = 16; o; o >>= 1) m = fmaxf(m, __shfl_xor_sync(0xffffffffu, m, o));
                float e0 = expf(v0 - m), e1 = expf(v1 - m), e2 = expf(v2 - m), e3 = expf(v3 - m);
                float s = e0 + e1 + e2 + e3;
#pragma unroll
                for (int o = 16; o; o >>= 1) s += __shfl_xor_sync(0xffffffffu, s, o);
                float inv = 1.0f / s;
                sw[lane] = e0 * inv; sw[lane + 32] = e1 * inv;
                sw[lane + 64] = e2 * inv; sw[lane + 96] = e3 * inv;
            }
            __syncthreads();
            if (tid < Sc) att[((size_t)b * Tc + t) * Sc + tid] = sw[tid];
            {
                int c0 = tid, c1 = tid + 256;
                const float* e0p = enc + (size_t)b * Sc * Hc + c0;
                const float* e1p = enc + (size_t)b * Sc * Hc + c1;
                float a0 = 0.f, a1 = 0.f;
#pragma unroll 8
                for (int s = 0; s < Sc; s++) {
                    float w = sw[s];
                    a0 += w * e0p[(size_t)s * Hc];
                    a1 += w * e1p[(size_t)s * Hc];
                }
                split2(a0, g_ctxH + b * Hc + c0, g_ctxL + b * Hc + c0);
                split2(a1, g_ctxH + b * Hc + c1, g_ctxL + b * Hc + c1);
            }
        }
        GRID_BAR();

        // -- phase 3: giC partials = ctx @ WihC^T : 12 n-tiles x 4 K-splits ---
        if (bid < 48) {
            int n0 = (bid % 12) * 128, kz = bid / 12;
            mma_tile(sm, g_ctxH, g_ctxL, g_WihCH, g_WihCL, nullptr,
                     g_giC4 + (size_t)kz * Bc * 1536,
                     0, n0, kz * 128, 128 / KC2, 1536, 3);
        }
        GRID_BAR();

        // -- phase 4: gates (block = batch row, 2 j per thread) ---------------
        {
            int b = bid;
            size_t r = (size_t)t * Bc + b;
#pragma unroll
            for (int jj = 0; jj < 2; jj++) {
                int j = tid + jj * 256;
                float ghr = 0.f, ghz = 0.f, ghn = 0.f, cr = 0.f, cz = 0.f, cn = 0.f;
#pragma unroll
                for (int p = 0; p < 4; p++) {
                    const float* A4 = g_A4 + (size_t)p * Bc * 2048 + b * 2048 + 512;
                    ghr += A4[j]; ghz += A4[Hc + j]; ghn += A4[2 * Hc + j];
                    const float* C4 = g_giC4 + (size_t)p * Bc * 1536 + b * 1536;
                    cr += C4[j]; cz += C4[Hc + j]; cn += C4[2 * Hc + j];
                }
                const float* giE = g_giE + r * (3 * Hc);
                float rr = sigm(giE[j] + cr + b_ih[j] + ghr + b_hh[j]);
                float z  = sigm(giE[Hc + j] + cz + b_ih[Hc + j] + ghz + b_hh[Hc + j]);
                float n  = tanhf(giE[2 * Hc + j] + cn + b_ih[2 * Hc + j]
                                 + rr * (ghn + b_hh[2 * Hc + j]));
                float hp = g_h[b * Hc + j];
                float hn = (1.0f - z) * n + z * hp;
                g_h[b * Hc + j] = hn;
                split2(hn, g_hhi + b * Hc + j, g_hlo + b * Hc + j);
                g_hallH[r * Hc + j] = __float2bfloat16(hn);
            }
        }
        GRID_BAR();

        // publish progress for logits blocks
        if (bid == 0 && tid == 0) {
            unsigned int tv = (unsigned int)(t + 1);
            asm volatile("st.release.gpu.global.u32 [%0], %1;"
                         :: "l"(&g_tstep), "r"(tv) : "memory");
        }
    }
#undef GRID_BAR
}

// ---------------- subtract log-sum per row ------------------------------------
__global__ __launch_bounds__(512) void sub_kernel(float* __restrict__ base)
{
    int r = blockIdx.x;
    float ls = logf(g_rowsum[r]);
    float4* row = (float4*)(base + (size_t)r * Vc);
    const int NV4 = Vc / 4;   // 8000
    for (int v = threadIdx.x; v < NV4; v += 512) {
        float4 x = row[v];
        x.x -= ls; x.y -= ls; x.z -= ls; x.w -= ls;
        row[v] = x;
    }
}

// ---------------- launch ----------------
extern "C" void kernel_launch(void* const* d_in, const int* in_sizes, int n_in,
                              void* d_out, int out_size)
{
    const float* enc  = (const float*)d_in[0];
    const float* h0   = (const float*)d_in[1];
    const int*   tgt  = (const int*)d_in[2];
    const float* emb  = (const float*)d_in[3];
    const float* Wa   = (const float*)d_in[4];
    const float* ba   = (const float*)d_in[5];
    const float* Ua   = (const float*)d_in[6];
    const float* bu   = (const float*)d_in[7];
    const float* Va   = (const float*)d_in[8];
    /* d_in[9] = bv : cancels inside softmax, never observable */
    const float* W_ih = (const float*)d_in[10];
    const float* W_hh = (const float*)d_in[11];
    const float* b_ih = (const float*)d_in[12];
    const float* b_hh = (const float*)d_in[13];
    const float* Wout = (const float*)d_in[14];
    const float* bout = (const float*)d_in[15];

    float* out  = (float*)d_out;
    float* logp = out;                                    // [B,T,V]
    float* hf   = out + (size_t)Bc * Tc * Vc;             // [1,B,H]
    float* att  = hf + (size_t)Bc * Hc;                   // [B,T,S]

    void *p_encH, *p_encL, *p_UaTH, *p_UaTL, *p_xeH, *p_xeL;
    void *p_WihEH, *p_WihEL, *p_Uk, *p_giE;
    cudaGetSymbolAddress(&p_encH, g_encH);   cudaGetSymbolAddress(&p_encL, g_encL);
    cudaGetSymbolAddress(&p_UaTH, g_UaTH);   cudaGetSymbolAddress(&p_UaTL, g_UaTL);
    cudaGetSymbolAddress(&p_xeH, g_xeH);     cudaGetSymbolAddress(&p_xeL, g_xeL);
    cudaGetSymbolAddress(&p_WihEH, g_WihEH); cudaGetSymbolAddress(&p_WihEL, g_WihEL);
    cudaGetSymbolAddress(&p_Uk, g_Uk);       cudaGetSymbolAddress(&p_giE, g_giE);

    // launch 1: ALL setup work fused
    prep_kernel<<<PR_XE, 256>>>(Wout, W_hh, Wa, Ua, W_ih, enc, h0, emb, tgt);

    const int MMA_SMEM = 2 * STG2 * 2;   // 61.4 KB dynamic
    cudaFuncSetAttribute(mma_nt_kernel, cudaFuncAttributeMaxDynamicSharedMemorySize,
                         MMA_SMEM);
    // launch 2: Uk = enc @ UaT^T + bu : M=8192, N=512, K=512
    mma_nt_kernel<<<dim3(4, 128), 256, MMA_SMEM>>>((bf16*)p_encH, (bf16*)p_encL,
                                                   (bf16*)p_UaTH, (bf16*)p_UaTL,
                                                   bu, (float*)p_Uk, Hc, (size_t)Hc, 3);
    // launch 3: giE = xe @ WihE^T : M=4096, N=1536, K=512
    mma_nt_kernel<<<dim3(12, 64), 256, MMA_SMEM>>>((bf16*)p_xeH, (bf16*)p_xeL,
                                                   (bf16*)p_WihEH, (bf16*)p_WihEL,
                                                   nullptr, (float*)p_giE,
                                                   Hc, (size_t)(3 * Hc), 3);

    // launch 4: loop + overlapped logits (1 block/SM via 120KB smem)
    cudaFuncSetAttribute(mega_kernel, cudaFuncAttributeMaxDynamicSharedMemorySize,
                         MEGA_SMEM);
    mega_kernel<<<NBLK + NLOGITS, 256, MEGA_SMEM>>>(enc, Va, ba, b_ih, b_hh, bout,
                                                    att, logp);

    // launch 5: log_softmax finalize
    sub_kernel<<<Bc * Tc, 512>>>(logp);

    // launch 6: final hidden state
    final_h_kernel<<<(Bc * Hc + 255) / 256, 256>>>(hf);
}

// round 16
// speedup vs baseline: 1.6750x; 1.0165x over previous
#include <cuda_runtime.h>
#include <cuda_bf16.h>
#include <math.h>
#include <stdint.h>

#define Bc 64
#define Sc 128
#define Tc 64
#define Hc 512
#define Vc 32000
#define NBLK 64
#define NLOGITS (16 * 250)   // 16 m-tiles (M=256) x 250 n-tiles
#define MEGA_SMEM (165 * 1024)

typedef __nv_bfloat16 bf16;

// ---------------- scratch (device globals: no allocs allowed) ----------------
__device__ __align__(16) float g_Uk[(size_t)Bc * Sc * Hc];       // 16 MB
__device__ __align__(16) float g_h[Bc * Hc];
__device__ __align__(16) bf16  g_hhi[Bc * Hc], g_hlo[Bc * Hc];
__device__ __align__(16) float g_A4[4 * Bc * 2048];              // K-split partials [hwa|gh]
__device__ __align__(16) float g_giC4[4 * Bc * 1536];            // K-split partials giC
__device__ __align__(16) float g_giE[(size_t)Tc * Bc * 3 * Hc];  // 25 MB
__device__ __align__(16) bf16  g_xeH[(size_t)Tc * Bc * Hc], g_xeL[(size_t)Tc * Bc * Hc];
__device__ __align__(16) bf16  g_ctxH[Bc * Hc], g_ctxL[Bc * Hc];
__device__ __align__(16) bf16  g_hallH[(size_t)Tc * Bc * Hc];
__device__ __align__(16) bf16  g_WoutH[(size_t)Vc * Hc], g_WoutL[(size_t)Vc * Hc];
__device__ __align__(16) bf16  g_BcatH[2048 * Hc], g_BcatL[2048 * Hc]; // [WaT|W_hh]
__device__ __align__(16) bf16  g_WihEH[3 * Hc * Hc], g_WihEL[3 * Hc * Hc];
__device__ __align__(16) bf16  g_WihCH[3 * Hc * Hc], g_WihCL[3 * Hc * Hc];
__device__ __align__(16) bf16  g_UaTH[Hc * Hc], g_UaTL[Hc * Hc];
__device__ __align__(16) bf16  g_encH[(size_t)Bc * Sc * Hc], g_encL[(size_t)Bc * Sc * Hc];
__device__ float g_rowsum[Bc * Tc];   // per-output-row sum of exp(logits)
__device__ unsigned int g_barrier;
__device__ unsigned int g_tstep;

__device__ __forceinline__ float sigm(float x) { return 1.0f / (1.0f + expf(-x)); }
__device__ __forceinline__ float fast_tanh(float x) {
    float y; asm("tanh.approx.f32 %0, %1;" : "=f"(y) : "f"(x)); return y;
}
__device__ __forceinline__ void split2(float x, bf16* hi, bf16* lo) {
    bf16 h = __float2bfloat16(x);
    *hi = h;
    *lo = __float2bfloat16(x - __bfloat162float(h));
}
__device__ __forceinline__ void split4(float4 v, bf16* hi, bf16* lo) {
    bf16 h0 = __float2bfloat16(v.x), h1 = __float2bfloat16(v.y);
    bf16 h2 = __float2bfloat16(v.z), h3 = __float2bfloat16(v.w);
    bf16 l0 = __float2bfloat16(v.x - __bfloat162float(h0));
    bf16 l1 = __float2bfloat16(v.y - __bfloat162float(h1));
    bf16 l2 = __float2bfloat16(v.z - __bfloat162float(h2));
    bf16 l3 = __float2bfloat16(v.w - __bfloat162float(h3));
    __nv_bfloat162* H = (__nv_bfloat162*)hi;
    __nv_bfloat162* L = (__nv_bfloat162*)lo;
    H[0] = __halves2bfloat162(h0, h1);
    H[1] = __halves2bfloat162(h2, h3);
    L[0] = __halves2bfloat162(l0, l1);
    L[1] = __halves2bfloat162(l2, l3);
}
// FMA-pipe exp: 2^(x*log2e) via deg-5 poly.
__device__ __forceinline__ float fexp(float x) {
    float y = x * 1.44269504f;
    y = fminf(fmaxf(y, -60.f), 60.f);
    int i = __float2int_rn(y);
    float f = y - (float)i;
    float p = 1.3333558e-3f;
    p = fmaf(p, f, 9.618129e-3f);
    p = fmaf(p, f, 5.550411e-2f);
    p = fmaf(p, f, 2.402265e-1f);
    p = fmaf(p, f, 6.931472e-1f);
    p = fmaf(p, f, 1.0f);
    return p * __int_as_float((i + 127) << 23);
}

// ---------------- ONE fused prep kernel ----------------
#define PR_WOUT   16000
#define PR_WHH    (PR_WOUT + 768)
#define PR_WAT    (PR_WHH + 1024)
#define PR_UAT    (PR_WAT + 1024)
#define PR_WIH    (PR_UAT + 3072)
#define PR_ENC    (PR_WIH + 4096)
#define PR_INIT   (PR_ENC + 128)
#define PR_XE     (PR_INIT + 4096)

__global__ __launch_bounds__(256) void prep_kernel(
    const float* __restrict__ Wout, const float* __restrict__ W_hh,
    const float* __restrict__ Wa, const float* __restrict__ Ua,
    const float* __restrict__ W_ih, const float* __restrict__ enc,
    const float* __restrict__ h0, const float* __restrict__ emb,
    const int* __restrict__ tgt)
{
    int bid = blockIdx.x, tid = threadIdx.x;
    if (bid < PR_WOUT) {
        int i = (bid * 256 + tid) * 4;
        split4(*(const float4*)(Wout + i), g_WoutH + i, g_WoutL + i);
    } else if (bid < PR_WHH) {
        int i = ((bid - PR_WOUT) * 256 + tid) * 4;
        split4(*(const float4*)(W_hh + i), g_BcatH + 512 * Hc + i, g_BcatL + 512 * Hc + i);
    } else if (bid < PR_WAT) {
        int idx = (bid - PR_WHH) * 256 + tid;
        int k = idx >> 9, n = idx & 511;
        split2(Wa[idx], g_BcatH + n * Hc + k, g_BcatL + n * Hc + k);
    } else if (bid < PR_UAT) {
        int idx = (bid - PR_WAT) * 256 + tid;
        int k = idx >> 9, n = idx & 511;
        split2(Ua[idx], g_UaTH + n * Hc + k, g_UaTL + n * Hc + k);
    } else if (bid < PR_WIH) {
        int idx = (bid - PR_UAT) * 256 + tid;
        int r = idx >> 9, c = idx & 511;
        split2(W_ih[(size_t)r * 1024 + c], g_WihEH + idx, g_WihEL + idx);
        split2(W_ih[(size_t)r * 1024 + 512 + c], g_WihCH + idx, g_WihCL + idx);
    } else if (bid < PR_ENC) {
        int i = ((bid - PR_WIH) * 256 + tid) * 4;
        split4(*(const float4*)(enc + i), g_encH + i, g_encL + i);
    } else if (bid < PR_INIT) {
        int i = (bid - PR_ENC) * 256 + tid;
        if (i == 0) { g_barrier = 0u; g_tstep = 0u; }
        if (i < Bc * Tc) g_rowsum[i] = 0.f;
        float v = h0[i];
        g_h[i] = v;
        split2(v, g_hhi + i, g_hlo + i);
    } else {
        int idx = bid - PR_INIT;
        int t = idx >> 6, b = idx & 63;
        int tok = (t == 0) ? 0 : tgt[b * Tc + t - 1];
        size_t base = ((size_t)t * Bc + b) * Hc;
        const float* e = emb + (size_t)tok * Hc;
        for (int k = tid; k < Hc; k += 256)
            split2(e[k], g_xeH + base + k, g_xeL + base + k);
    }
}

__global__ void final_h_kernel(float* __restrict__ dst) {
    int i = blockIdx.x * 256 + threadIdx.x;
    if (i < Bc * Hc) dst[i] = g_h[i];
}

// ---------------- MMA building blocks -----------------------------------------
#define MMA_BF16(c, a, b0_, b1_)                                           \
    asm volatile(                                                          \
        "mma.sync.aligned.m16n8k16.row.col.f32.bf16.bf16.f32 "             \
        "{%0,%1,%2,%3},{%4,%5,%6,%7},{%8,%9},{%0,%1,%2,%3};"               \
        : "+f"(c[0]), "+f"(c[1]), "+f"(c[2]), "+f"(c[3])                   \
        : "r"(a[0]), "r"(a[1]), "r"(a[2]), "r"(a[3]), "r"(b0_), "r"(b1_))

#define LDSM4(r, addr)                                                     \
    asm volatile("ldmatrix.sync.aligned.m8n8.x4.shared.b16 {%0,%1,%2,%3}, [%4];" \
        : "=r"(r[0]), "=r"(r[1]), "=r"(r[2]), "=r"(r[3]) : "r"(addr))

__device__ __forceinline__ void cpa16(uint32_t dst, const void* src) {
    asm volatile("cp.async.ca.shared.global [%0], [%1], 16;" :: "r"(dst), "l"(src));
}
__device__ __forceinline__ void cpa16_ef(uint32_t dst, const void* src, uint64_t pol) {
    asm volatile("cp.async.ca.shared.global.L2::cache_hint [%0], [%1], 16, %2;"
                 :: "r"(dst), "l"(src), "l"(pol));
}

// ---- KC=32 streaming tile (setup GEMMs: Uk, giE) ----
#define KC2 32
#define PAD2 40
#define O2_AH 0
#define O2_AL (64 * PAD2)
#define O2_BH (128 * PAD2)
#define O2_BL (256 * PAD2)
#define STG2  (384 * PAD2)

__device__ __forceinline__ void mma_tile(
    bf16* sm, const bf16* Ahi, const bf16* Alo,
    const bf16* Bhi, const bf16* Blo,
    const float* bias, float* out,
    int m0, int n0, int kb, int niters, size_t ldc, int nterms)
{
    uint32_t sb = (uint32_t)__cvta_generic_to_shared(sm);
    int tid = threadIdx.x, lane = tid & 31, wid = tid >> 5;
    int g = lane >> 2, t4 = lane & 3;
    int wy = wid & 3, wx = wid >> 2;

    int arow = tid >> 2, ac8 = (tid & 3) * 8;
    const bf16* ahp = Ahi + (size_t)(m0 + arow) * 512 + ac8;
    const bf16* alp = Alo + (size_t)(m0 + arow) * 512 + ac8;
    uint32_t ahd = sb + 2 * (O2_AH + arow * PAD2 + ac8);
    uint32_t ald = sb + 2 * (O2_AL + arow * PAD2 + ac8);
    int b0r = tid >> 2, b1r = 64 + (tid >> 2), bc8 = (tid & 3) * 8;
    const bf16* bh0 = Bhi + (size_t)(n0 + b0r) * 512 + bc8;
    const bf16* bh1 = Bhi + (size_t)(n0 + b1r) * 512 + bc8;
    const bf16* bl0 = Blo + (size_t)(n0 + b0r) * 512 + bc8;
    const bf16* bl1 = Blo + (size_t)(n0 + b1r) * 512 + bc8;
    uint32_t bh0d = sb + 2 * (O2_BH + b0r * PAD2 + bc8);
    uint32_t bh1d = sb + 2 * (O2_BH + b1r * PAD2 + bc8);
    uint32_t bl0d = sb + 2 * (O2_BL + b0r * PAD2 + bc8);
    uint32_t bl1d = sb + 2 * (O2_BL + b1r * PAD2 + bc8);

    int la = (wy * 16 + (lane & 15)) * PAD2 + (lane >> 4) * 8;
    int nloc = (lane & 7) | ((lane & 16) >> 1);
    int kq2 = ((lane >> 3) & 1) * 8;
    int lb = (wx * 64 + nloc) * PAD2 + kq2;

    float acc[8][4] = {};

    cpa16(ahd, ahp + kb);
    if (nterms == 3) cpa16(ald, alp + kb);
    cpa16(bh0d, bh0 + kb);
    cpa16(bh1d, bh1 + kb);
    cpa16(bl0d, bl0 + kb);
    cpa16(bl1d, bl1 + kb);
    asm volatile("cp.async.commit_group;");

    int st = 0;
    for (int it = 0; it < niters; it++) {
        if (it + 1 < niters) {
            int kn = kb + (it + 1) * KC2;
            uint32_t so = (uint32_t)((st ^ 1) * STG2 * 2);
            cpa16(ahd + so, ahp + kn);
            if (nterms == 3) cpa16(ald + so, alp + kn);
            cpa16(bh0d + so, bh0 + kn);
            cpa16(bh1d + so, bh1 + kn);
            cpa16(bl0d + so, bl0 + kn);
            cpa16(bl1d + so, bl1 + kn);
            asm volatile("cp.async.commit_group;");
            asm volatile("cp.async.wait_group 1;");
        } else {
            asm volatile("cp.async.wait_group 0;");
        }
        __syncthreads();

        uint32_t stoff = (uint32_t)(st * STG2 * 2);
#pragma unroll
        for (int kf = 0; kf < 2; kf++) {
            int ko = kf * 16;
            uint32_t aH[4], aL[4];
            LDSM4(aH, sb + stoff + 2 * (O2_AH + la + ko));
            if (nterms == 3) LDSM4(aL, sb + stoff + 2 * (O2_AL + la + ko));
#pragma unroll
            for (int q = 0; q < 4; q++) {
                uint32_t bH[4], bL[4];
                LDSM4(bH, sb + stoff + 2 * (O2_BH + lb + q * 16 * PAD2 + ko));
                LDSM4(bL, sb + stoff + 2 * (O2_BL + lb + q * 16 * PAD2 + ko));
                MMA_BF16(acc[2 * q],     aH, bH[0], bH[1]);
                MMA_BF16(acc[2 * q + 1], aH, bH[2], bH[3]);
                MMA_BF16(acc[2 * q],     aH, bL[0], bL[1]);
                MMA_BF16(acc[2 * q + 1], aH, bL[2], bL[3]);
                if (nterms == 3) {
                    MMA_BF16(acc[2 * q],     aL, bH[0], bH[1]);
                    MMA_BF16(acc[2 * q + 1], aL, bH[2], bH[3]);
                }
            }
        }
        __syncthreads();
        st ^= 1;
    }

    int mr0 = m0 + wy * 16 + g, mr1 = mr0 + 8;
    size_t ro0 = (size_t)mr0 * ldc, ro1 = (size_t)mr1 * ldc;
#pragma unroll
    for (int nf = 0; nf < 8; nf++) {
        int col = n0 + wx * 64 + nf * 8 + t4 * 2;
        float b0 = bias ? bias[col] : 0.f;
        float b1 = bias ? bias[col + 1] : 0.f;
        out[ro0 + col]     = acc[nf][0] + b0;
        out[ro0 + col + 1] = acc[nf][1] + b1;
        out[ro1 + col]     = acc[nf][2] + b0;
        out[ro1 + col + 1] = acc[nf][3] + b1;
    }
}

__global__ __launch_bounds__(256) void mma_nt_kernel(
    const bf16* __restrict__ Ahi, const bf16* __restrict__ Alo,
    const bf16* __restrict__ Bhi, const bf16* __restrict__ Blo,
    const float* __restrict__ bias, float* __restrict__ out,
    int Kcp, size_t ldc, int nterms)
{
    extern __shared__ __align__(16) bf16 smd[];
    mma_tile(smd, Ahi, Alo, Bhi, Blo, bias, out,
             blockIdx.y * 64, blockIdx.x * 128, 0, Kcp / KC2, ldc, nterms);
}

// ---- resident-B loop smem layout (elem offsets in mega loop blocks) ----
// B slices stored 128 rows x 136 (128 data + 8 pad): row stride 272B ->
// ldmatrix bank stride 4*r, conflict-free. Pad region never read.
#define PADB 136
#define RB_BCH 0                         // Bcat hi slice   (17408 elems)
#define RB_BCL 17408                     // Bcat lo
#define RB_WCH 34816                     // WihC hi (blocks 0..47)
#define RB_WCL 52224                     // WihC lo
#define RA_ST  69632                     // A double-buffer stages
#define RA_STG 5120                      // per stage: hi 64x40 + lo 64x40
#define RF_MISC (RA_ST + 2 * RA_STG)     // float scratch after stages

// 64x128 tile vs resident B slice; streams A only (h or ctx hi/lo), K=128.
__device__ __forceinline__ void mma_res(
    bf16* sm, uint32_t sb, int bresH, int bresL,
    const bf16* Ahi, const bf16* Alo,
    float* out, int kb, int n0, size_t ldc)
{
    int tid = threadIdx.x, lane = tid & 31, wid = tid >> 5;
    int g = lane >> 2, t4 = lane & 3;
    int wy = wid & 3, wx = wid >> 2;

    int arow = tid >> 2, ac8 = (tid & 3) * 8;
    const bf16* ahp = Ahi + (size_t)arow * 512 + ac8;
    const bf16* alp = Alo + (size_t)arow * 512 + ac8;
    uint32_t ahd = sb + 2 * (RA_ST + arow * PAD2 + ac8);
    uint32_t ald = sb + 2 * (RA_ST + 64 * PAD2 + arow * PAD2 + ac8);

    int la = (wy * 16 + (lane & 15)) * PAD2 + (lane >> 4) * 8;
    int nloc = (lane & 7) | ((lane & 16) >> 1);
    int kq2 = ((lane >> 3) & 1) * 8;
    int lbB = (wx * 64 + nloc) * PADB + kq2;

    float acc[8][4] = {};

    cpa16(ahd, ahp + kb);
    cpa16(ald, alp + kb);
    asm volatile("cp.async.commit_group;");

    int st = 0;
#pragma unroll
    for (int it = 0; it < 4; it++) {
        if (it + 1 < 4) {
            int kn = kb + (it + 1) * 32;
            uint32_t so = (uint32_t)((st ^ 1) * RA_STG * 2);
            cpa16(ahd + so, ahp + kn);
            cpa16(ald + so, alp + kn);
            asm volatile("cp.async.commit_group;");
            asm volatile("cp.async.wait_group 1;");
        } else {
            asm volatile("cp.async.wait_group 0;");
        }
        __syncthreads();

        uint32_t ast = (uint32_t)(st * RA_STG * 2);
#pragma unroll
        for (int kf = 0; kf < 2; kf++) {
            int ko = kf * 16;
            int kres = it * 32 + ko;
            uint32_t aH[4], aL[4];
            LDSM4(aH, sb + ast + 2 * (RA_ST + la + ko));
            LDSM4(aL, sb + ast + 2 * (RA_ST + 64 * PAD2 + la + ko));
#pragma unroll
            for (int q = 0; q < 4; q++) {
                uint32_t bH[4], bL[4];
                LDSM4(bH, sb + 2 * (bresH + lbB + q * 16 * PADB + kres));
                LDSM4(bL, sb + 2 * (bresL + lbB + q * 16 * PADB + kres));
                MMA_BF16(acc[2 * q],     aH, bH[0], bH[1]);
                MMA_BF16(acc[2 * q + 1], aH, bH[2], bH[3]);
                MMA_BF16(acc[2 * q],     aH, bL[0], bL[1]);
                MMA_BF16(acc[2 * q + 1], aH, bL[2], bL[3]);
                MMA_BF16(acc[2 * q],     aL, bH[0], bH[1]);
                MMA_BF16(acc[2 * q + 1], aL, bH[2], bH[3]);
            }
        }
        __syncthreads();
        st ^= 1;
    }

    int mr0 = wy * 16 + g, mr1 = mr0 + 8;
    size_t ro0 = (size_t)mr0 * ldc, ro1 = (size_t)mr1 * ldc;
#pragma unroll
    for (int nf = 0; nf < 8; nf++) {
        int col = n0 + wx * 64 + nf * 8 + t4 * 2;
        out[ro0 + col]     = acc[nf][0];
        out[ro0 + col + 1] = acc[nf][1];
        out[ro1 + col]     = acc[nf][2];
        out[ro1 + col + 1] = acc[nf][3];
    }
}

// ---------------- logits tile M=256 (KC=16, pad 24 — unchanged) --------------
#define KC 16
#define LDApad 24
#define L2_AH 0
#define L2_BH (256 * LDApad)
#define L2_BL (384 * LDApad)
#define L2_STG (512 * LDApad)

__device__ __forceinline__ void logits_tile256(
    bf16* sm, const bf16* Ahi, const bf16* Bhi, const bf16* Blo,
    const float* bias, float* out, int m0, int n0)
{
    uint32_t sb = (uint32_t)__cvta_generic_to_shared(sm);
    int tid = threadIdx.x, lane = tid & 31, wid = tid >> 5;
    int g = lane >> 2, t4 = lane & 3;
    int wy = wid & 3, wx = wid >> 2;

    uint64_t pol;
    asm volatile("createpolicy.fractional.L2::evict_first.b64 %0, 1.0;" : "=l"(pol));

    int ar = tid >> 1, ao = (tid & 1) * 8;
    const bf16* ap0 = Ahi + (size_t)(m0 + ar) * 512 + ao;
    const bf16* ap1 = ap0 + (size_t)128 * 512;
    uint32_t ad0 = sb + 2 * (L2_AH + ar * LDApad + ao);
    uint32_t ad1 = ad0 + 2 * (128 * LDApad);
    const bf16* bhp = Bhi + (size_t)(n0 + ar) * 512 + ao;
    const bf16* blp = Blo + (size_t)(n0 + ar) * 512 + ao;
    uint32_t bhd = sb + 2 * (L2_BH + ar * LDApad + ao);
    uint32_t bld = sb + 2 * (L2_BL + ar * LDApad + ao);

    int la = (wy * 16 + (lane & 15)) * LDApad + (lane >> 4) * 8;
    int nloc = (lane & 7) | ((lane & 16) >> 1);
    int kq2 = ((lane >> 3) & 1) * 8;
    int lb = (wx * 64 + nloc) * LDApad + kq2;

    float acc[4][8][4] = {};

    cpa16_ef(ad0, ap0, pol);
    cpa16_ef(ad1, ap1, pol);
    cpa16_ef(bhd, bhp, pol);
    cpa16_ef(bld, blp, pol);
    asm volatile("cp.async.commit_group;");

    int st = 0;
    const int niters = Hc / KC;   // 32
    for (int it = 0; it < niters; it++) {
        if (it + 1 < niters) {
            int kn = (it + 1) * KC;
            uint32_t so = (uint32_t)((st ^ 1) * L2_STG * 2);
            cpa16_ef(ad0 + so, ap0 + kn, pol);
            cpa16_ef(ad1 + so, ap1 + kn, pol);
            cpa16_ef(bhd + so, bhp + kn, pol);
            cpa16_ef(bld + so, blp + kn, pol);
            asm volatile("cp.async.commit_group;");
            asm volatile("cp.async.wait_group 1;");
        } else {
            asm volatile("cp.async.wait_group 0;");
        }
        __syncthreads();

        uint32_t stoff = (uint32_t)(st * L2_STG * 2);
        uint32_t aH[4][4];
#pragma unroll
        for (int ms = 0; ms < 4; ms++)
            LDSM4(aH[ms], sb + stoff + 2 * (L2_AH + ms * 64 * LDApad + la));
#pragma unroll
        for (int q = 0; q < 4; q++) {
            uint32_t bH[4], bL[4];
            LDSM4(bH, sb + stoff + 2 * (L2_BH + lb + q * 16 * LDApad));
            LDSM4(bL, sb + stoff + 2 * (L2_BL + lb + q * 16 * LDApad));
#pragma unroll
            for (int ms = 0; ms < 4; ms++) {
                MMA_BF16(acc[ms][2 * q],     aH[ms], bH[0], bH[1]);
                MMA_BF16(acc[ms][2 * q + 1], aH[ms], bH[2], bH[3]);
                MMA_BF16(acc[ms][2 * q],     aH[ms], bL[0], bL[1]);
                MMA_BF16(acc[ms][2 * q + 1], aH[ms], bL[2], bL[3]);
            }
        }
        __syncthreads();
        st ^= 1;
    }

#pragma unroll
    for (int ms = 0; ms < 4; ms++) {
        int mr0 = m0 + ms * 64 + wy * 16 + g, mr1 = mr0 + 8;
        int r0 = (mr0 & 63) * Tc + (mr0 >> 6);
        int r1 = (mr1 & 63) * Tc + (mr1 >> 6);
        size_t ro0 = (size_t)r0 * Vc, ro1 = (size_t)r1 * Vc;
        float es0 = 0.f, es1 = 0.f;
#pragma unroll
        for (int nf = 0; nf < 8; nf++) {
            int col = n0 + wx * 64 + nf * 8 + t4 * 2;
            float b0 = bias[col], b1 = bias[col + 1];
            float v00 = acc[ms][nf][0] + b0, v01 = acc[ms][nf][1] + b1;
            float v10 = acc[ms][nf][2] + b0, v11 = acc[ms][nf][3] + b1;
            out[ro0 + col]     = v00;
            out[ro0 + col + 1] = v01;
            out[ro1 + col]     = v10;
            out[ro1 + col + 1] = v11;
            es0 += fexp(v00) + fexp(v01);
            es1 += fexp(v10) + fexp(v11);
        }
        es0 += __shfl_xor_sync(0xffffffffu, es0, 1);
        es0 += __shfl_xor_sync(0xffffffffu, es0, 2);
        es1 += __shfl_xor_sync(0xffffffffu, es1, 1);
        es1 += __shfl_xor_sync(0xffffffffu, es1, 2);
        if (t4 == 0) {
            atomicAdd(&g_rowsum[r0], es0);
            atomicAdd(&g_rowsum[r1], es1);
        }
    }
}

// ---------------- megakernel: resident-weight loop + overlapped logits --------
__global__ __launch_bounds__(256) void mega_kernel(
    const float* __restrict__ enc, const float* __restrict__ Va,
    const float* __restrict__ ba, const float* __restrict__ b_ih,
    const float* __restrict__ b_hh, const float* __restrict__ bout,
    float* __restrict__ att, float* __restrict__ logp)
{
    extern __shared__ __align__(16) bf16 sm[];
    int bid = blockIdx.x, tid = threadIdx.x;

    if (bid >= NBLK) {
        // ---------------- logits role (M=256 tiles) ----------------
        int job = bid - NBLK;
        int my = job / 250, nx = job % 250;
        unsigned int need = 4 * my + 4;
        if (tid == 0) {
            unsigned int v;
            for (;;) {
                asm volatile("ld.acquire.gpu.global.u32 %0, [%1];"
                             : "=r"(v) : "l"(&g_tstep) : "memory");
                if (v >= need) break;
                asm volatile("nanosleep.u32 4000;");
            }
        }
        __syncthreads();
        logits_tile256(sm, g_hallH, g_WoutH, g_WoutL, bout, logp, my * 256, nx * 128);
        return;
    }

    // ---------------- loop role ----------------
    int lane = tid & 31, warp = tid >> 5;
    unsigned int gen = 0;
    uint32_t sb = (uint32_t)__cvta_generic_to_shared(sm);
    float* smf = (float*)(sm + RF_MISC);
    float* shwa = smf;          // 512
    float* sva  = smf + 512;    // 512
    float* sw   = smf + 1024;   // 128

    // ---- one-time preload of resident weight slices ----
    {
        int n0 = (bid & 15) * 128, kz = bid >> 4;
        const bf16* srcH = g_BcatH + (size_t)n0 * 512 + kz * 128;
        const bf16* srcL = g_BcatL + (size_t)n0 * 512 + kz * 128;
        for (int c = tid; c < 2048; c += 256) {
            int row = c >> 4, off = (c & 15) * 8;
            cpa16(sb + 2 * (RB_BCH + row * PADB + off), srcH + (size_t)row * 512 + off);
            cpa16(sb + 2 * (RB_BCL + row * PADB + off), srcL + (size_t)row * 512 + off);
        }
        if (bid < 48) {
            int n0c = (bid % 12) * 128, kzc = bid / 12;
            const bf16* sH = g_WihCH + (size_t)n0c * 512 + kzc * 128;
            const bf16* sL = g_WihCL + (size_t)n0c * 512 + kzc * 128;
            for (int c = tid; c < 2048; c += 256) {
                int row = c >> 4, off = (c & 15) * 8;
                cpa16(sb + 2 * (RB_WCH + row * PADB + off), sH + (size_t)row * 512 + off);
                cpa16(sb + 2 * (RB_WCL + row * PADB + off), sL + (size_t)row * 512 + off);
            }
        }
        asm volatile("cp.async.commit_group;");
        asm volatile("cp.async.wait_group 0;");
        __syncthreads();
    }

#define GRID_BAR()                                                             \
    do {                                                                       \
        __syncthreads();                                                       \
        gen += NBLK;                                                           \
        if (tid == 0) {                                                        \
            asm volatile("red.release.gpu.global.add.u32 [%0], 1;"             \
                         :: "l"(&g_barrier) : "memory");                       \
            unsigned int v;                                                    \
            do {                                                               \
                asm volatile("ld.acquire.gpu.global.u32 %0, [%1];"             \
                             : "=r"(v) : "l"(&g_barrier) : "memory");          \
            } while (v < gen);                                                 \
        }                                                                      \
        __syncthreads();                                                       \
    } while (0)

    for (int t = 0; t < Tc; t++) {
        // -- phase 1: [hwa|gh] partials = h @ Bcat^T (resident B slice) -------
        {
            int n0 = (bid & 15) * 128, kz = bid >> 4;
            mma_res(sm, sb, RB_BCH, RB_BCL, g_hhi, g_hlo,
                    g_A4 + (size_t)kz * Bc * 2048, kz * 128, n0, 2048);
        }
        GRID_BAR();

        // -- phase 2: fused scores + softmax + ctx (block = batch row) --------
        {
            int b = bid;
            for (int i = tid; i < Hc; i += 256) {
                float v = ba[i];
#pragma unroll
                for (int p = 0; p < 4; p++) v += g_A4[(size_t)p * Bc * 2048 + b * 2048 + i];
                shwa[i] = v;
                sva[i] = Va[i];
            }
            __syncthreads();
#pragma unroll 2
            for (int si = 0; si < 16; si++) {
                int s = warp * 16 + si;
                const float* uk = g_Uk + ((size_t)b * Sc + s) * Hc;
                float acc = 0.f;
#pragma unroll
                for (int j = 0; j < 4; j++) {
                    int k = j * 128 + lane * 4;
                    float4 u  = *(const float4*)(uk + k);
                    float4 wv = *(const float4*)(shwa + k);
                    float4 vv = *(const float4*)(sva + k);
                    acc += fast_tanh(wv.x + u.x) * vv.x + fast_tanh(wv.y + u.y) * vv.y
                         + fast_tanh(wv.z + u.z) * vv.z + fast_tanh(wv.w + u.w) * vv.w;
                }
#pragma unroll
                for (int o = 16; o; o >>= 1) acc += __shfl_xor_sync(0xffffffffu, acc, o);
                if (!lane) sw[s] = acc;    // bv cancels in softmax
            }
            __syncthreads();
            if (warp == 0) {
                float v0 = sw[lane], v1 = sw[lane + 32], v2 = sw[lane + 64], v3 = sw[lane + 96];
                float m = fmaxf(fmaxf(v0, v1), fmaxf(v2, v3));
#pragma unroll
                for (int o = 16; o; o >>= 1) m = fmaxf(m, __shfl_xor_sync(0xffffffffu, m, o));
                float e0 = expf(v0 - m), e1 = expf(v1 - m), e2 = expf(v2 - m), e3 = expf(v3 - m);
                float s = e0 + e1 + e2 + e3;
#pragma unroll
                for (int o = 16; o; o >>= 1) s += __shfl_xor_sync(0xffffffffu, s, o);
                float inv = 1.0f / s;
                sw[lane] = e0 * inv; sw[lane + 32] = e1 * inv;
                sw[lane + 64] = e2 * inv; sw[lane + 96] = e3 * inv;
            }
            __syncthreads();
            if (tid < Sc) att[((size_t)b * Tc + t) * Sc + tid] = sw[tid];
            {
                int c0 = tid, c1 = tid + 256;
                const float* e0p = enc + (size_t)b * Sc * Hc + c0;
                const float* e1p = enc + (size_t)b * Sc * Hc + c1;
                float a0 = 0.f, a1 = 0.f;
#pragma unroll 8
                for (int s = 0; s < Sc; s++) {
                    float w = sw[s];
                    a0 += w * e0p[(size_t)s * Hc];
                    a1 += w * e1p[(size_t)s * Hc];
                }
                split2(a0, g_ctxH + b * Hc + c0, g_ctxL + b * Hc + c0);
                split2(a1, g_ctxH + b * Hc + c1, g_ctxL + b * Hc + c1);
            }
        }
        GRID_BAR();

        // -- phase 3: giC partials = ctx @ WihC^T (resident B slice) ----------
        if (bid < 48) {
            int n0 = (bid % 12) * 128, kz = bid / 12;
            mma_res(sm, sb, RB_WCH, RB_WCL, g_ctxH, g_ctxL,
                    g_giC4 + (size_t)kz * Bc * 1536, kz * 128, n0, 1536);
        }
        GRID_BAR();

        // -- phase 4: gates (block = batch row, 2 j per thread) ---------------
        {
            int b = bid;
            size_t r = (size_t)t * Bc + b;
#pragma unroll
            for (int jj = 0; jj < 2; jj++) {
                int j = tid + jj * 256;
                float ghr = 0.f, ghz = 0.f, ghn = 0.f, cr = 0.f, cz = 0.f, cn = 0.f;
#pragma unroll
                for (int p = 0; p < 4; p++) {
                    const float* A4 = g_A4 + (size_t)p * Bc * 2048 + b * 2048 + 512;
                    ghr += A4[j]; ghz += A4[Hc + j]; ghn += A4[2 * Hc + j];
                    const float* C4 = g_giC4 + (size_t)p * Bc * 1536 + b * 1536;
                    cr += C4[j]; cz += C4[Hc + j]; cn += C4[2 * Hc + j];
                }
                const float* giE = g_giE + r * (3 * Hc);
                float rr = sigm(giE[j] + cr + b_ih[j] + ghr + b_hh[j]);
                float z  = sigm(giE[Hc + j] + cz + b_ih[Hc + j] + ghz + b_hh[Hc + j]);
                float n  = tanhf(giE[2 * Hc + j] + cn + b_ih[2 * Hc + j]
                                 + rr * (ghn + b_hh[2 * Hc + j]));
                float hp = g_h[b * Hc + j];
                float hn = (1.0f - z) * n + z * hp;
                g_h[b * Hc + j] = hn;
                split2(hn, g_hhi + b * Hc + j, g_hlo + b * Hc + j);
                g_hallH[r * Hc + j] = __float2bfloat16(hn);
            }
        }
        GRID_BAR();

        if (bid == 0 && tid == 0) {
            unsigned int tv = (unsigned int)(t + 1);
            asm volatile("st.release.gpu.global.u32 [%0], %1;"
                         :: "l"(&g_tstep), "r"(tv) : "memory");
        }
    }
#undef GRID_BAR
}

// ---------------- subtract log-sum per row ------------------------------------
__global__ __launch_bounds__(512) void sub_kernel(float* __restrict__ base)
{
    int r = blockIdx.x;
    float ls = logf(g_rowsum[r]);
    float4* row = (float4*)(base + (size_t)r * Vc);
    const int NV4 = Vc / 4;
    for (int v = threadIdx.x; v < NV4; v += 512) {
        float4 x = row[v];
        x.x -= ls; x.y -= ls; x.z -= ls; x.w -= ls;
        row[v] = x;
    }
}

// ---------------- launch ----------------
extern "C" void kernel_launch(void* const* d_in, const int* in_sizes, int n_in,
                              void* d_out, int out_size)
{
    const float* enc  = (const float*)d_in[0];
    const float* h0   = (const float*)d_in[1];
    const int*   tgt  = (const int*)d_in[2];
    const float* emb  = (const float*)d_in[3];
    const float* Wa   = (const float*)d_in[4];
    const float* ba   = (const float*)d_in[5];
    const float* Ua   = (const float*)d_in[6];
    const float* bu   = (const float*)d_in[7];
    const float* Va   = (const float*)d_in[8];
    /* d_in[9] = bv : cancels inside softmax, never observable */
    const float* W_ih = (const float*)d_in[10];
    const float* W_hh = (const float*)d_in[11];
    const float* b_ih = (const float*)d_in[12];
    const float* b_hh = (const float*)d_in[13];
    const float* Wout = (const float*)d_in[14];
    const float* bout = (const float*)d_in[15];

    float* out  = (float*)d_out;
    float* logp = out;                                    // [B,T,V]
    float* hf   = out + (size_t)Bc * Tc * Vc;             // [1,B,H]
    float* att  = hf + (size_t)Bc * Hc;                   // [B,T,S]

    void *p_encH, *p_encL, *p_UaTH, *p_UaTL, *p_xeH, *p_xeL;
    void *p_WihEH, *p_WihEL, *p_Uk, *p_giE;
    cudaGetSymbolAddress(&p_encH, g_encH);   cudaGetSymbolAddress(&p_encL, g_encL);
    cudaGetSymbolAddress(&p_UaTH, g_UaTH);   cudaGetSymbolAddress(&p_UaTL, g_UaTL);
    cudaGetSymbolAddress(&p_xeH, g_xeH);     cudaGetSymbolAddress(&p_xeL, g_xeL);
    cudaGetSymbolAddress(&p_WihEH, g_WihEH); cudaGetSymbolAddress(&p_WihEL, g_WihEL);
    cudaGetSymbolAddress(&p_Uk, g_Uk);       cudaGetSymbolAddress(&p_giE, g_giE);

    // launch 1: ALL setup work fused
    prep_kernel<<<PR_XE, 256>>>(Wout, W_hh, Wa, Ua, W_ih, enc, h0, emb, tgt);

    const int MMA_SMEM = 2 * STG2 * 2;   // 61.4 KB dynamic
    cudaFuncSetAttribute(mma_nt_kernel, cudaFuncAttributeMaxDynamicSharedMemorySize,
                         MMA_SMEM);
    // launch 2: Uk = enc @ UaT^T + bu
    mma_nt_kernel<<<dim3(4, 128), 256, MMA_SMEM>>>((bf16*)p_encH, (bf16*)p_encL,
                                                   (bf16*)p_UaTH, (bf16*)p_UaTL,
                                                   bu, (float*)p_Uk, Hc, (size_t)Hc, 3);
    // launch 3: giE = xe @ WihE^T
    mma_nt_kernel<<<dim3(12, 64), 256, MMA_SMEM>>>((bf16*)p_xeH, (bf16*)p_xeL,
                                                   (bf16*)p_WihEH, (bf16*)p_WihEL,
                                                   nullptr, (float*)p_giE,
                                                   Hc, (size_t)(3 * Hc), 3);

    // launch 4: loop (resident weights) + overlapped logits (1 block/SM)
    cudaFuncSetAttribute(mega_kernel, cudaFuncAttributeMaxDynamicSharedMemorySize,
                         MEGA_SMEM);
    mega_kernel<<<NBLK + NLOGITS, 256, MEGA_SMEM>>>(enc, Va, ba, b_ih, b_hh, bout,
                                                    att, logp);

    // launch 5: log_softmax finalize
    sub_kernel<<<Bc * Tc, 512>>>(logp);

    // launch 6: final hidden state
    final_h_kernel<<<(Bc * Hc + 255) / 256, 256>>>(hf);
}